// round 1
// baseline (speedup 1.0000x reference)
#include <cuda_runtime.h>
#include <math.h>

// ---------------- problem constants ----------------
#define CB   8       // batch
#define CS   1024    // seq len
#define CIN  256     // in dim
#define CD   512     // model dim
#define CH   8       // heads
#define CL   4       // layers
#define CM   256     // bank entries
#define CDFF 2048
#define CDH  64
#define NTOK (CB*CS) // 8192

// ---------------- scratch layout (floats) ----------------
constexpr long long O_H    = 0,                 S_H    = (long long)NTOK*CD;        // h
constexpr long long O_QKV  = O_H + S_H,         S_QKV  = (long long)NTOK*3*CD;      // qkv
constexpr long long O_SC   = O_QKV + S_QKV,     S_SC   = (long long)CB*CH*CS*CS;    // attn scores (reused for bank)
constexpr long long O_AO   = O_SC + S_SC,       S_AO   = (long long)NTOK*CD;        // attn out concat
constexpr long long O_FF   = O_AO + S_AO,       S_FF   = (long long)NTOK*CDFF;      // ff hidden
constexpr long long S_BNK  = (long long)CB*CM*CD;
constexpr long long O_BQ   = O_FF + S_FF;
constexpr long long O_BK   = O_BQ + S_BNK;
constexpr long long O_BV   = O_BK + S_BNK;
constexpr long long O_ZC   = O_BV + S_BNK;
constexpr long long O_Z    = O_ZC + S_BNK;
constexpr long long O_PD   = O_Z + S_BNK,       S_PD   = (long long)CB*CM*CM;       // Phi@Phi^T
constexpr long long O_P2   = O_PD + S_PD;                                           // [B*M]
constexpr long long O_KB   = O_P2 + CB*CM;                                          // [B*M]
constexpr long long O_HQ   = O_KB + CB*CM,      S_HQ   = (long long)NTOK*CD;
constexpr long long O_LG   = O_HQ + S_HQ,       S_LG   = (long long)NTOK*CM;
constexpr long long O_RT   = O_LG + S_LG,       S_RT   = (long long)NTOK*CD;
constexpr long long TOTAL_SCRATCH = O_RT + S_RT;   // ~121M floats ~ 484 MB

__device__ float g_scratch[TOTAL_SCRATCH];

// ---------------- generic strided-batched SGEMM ----------------
// C[m,n] = alpha * sum_k A[m,k] * (TRB ? B[n,k] : B[k,n])  (+bias[n]) (+Res[m,n]) (relu)
// batch z in grid.z decomposed as (zb, zh) = (z/Hb, z%Hb) with per-axis strides.
template<bool TRB, bool BIAS, bool RELU, bool RES>
__global__ __launch_bounds__(256)
void gemm_k(const float* __restrict__ A, const float* __restrict__ B,
            float* __restrict__ C, const float* __restrict__ bias,
            const float* __restrict__ Res,
            int Mr, int Nc, int Kd, int lda, int ldb, int ldc,
            int Hb,
            long long sAb, long long sAh, long long sBb, long long sBh,
            long long sCb, long long sCh, float alpha)
{
    int z  = blockIdx.z;
    int zb = z / Hb, zh = z - zb*Hb;
    A += (long long)zb*sAb + (long long)zh*sAh;
    B += (long long)zb*sBb + (long long)zh*sBh;
    C += (long long)zb*sCb + (long long)zh*sCh;
    const float* R = RES ? (Res + (long long)zb*sCb + (long long)zh*sCh) : nullptr;

    __shared__ float As[8][132];
    __shared__ float Bs[8][132];

    int m0 = blockIdx.y * 128;
    int n0 = blockIdx.x * 128;
    int tid = threadIdx.x;
    int tx = tid & 15, ty = tid >> 4;

    float acc[8][8];
    #pragma unroll
    for (int i = 0; i < 8; i++)
        #pragma unroll
        for (int j = 0; j < 8; j++) acc[i][j] = 0.f;

    for (int k0 = 0; k0 < Kd; k0 += 8) {
        #pragma unroll
        for (int it = 0; it < 4; it++) {
            int e = tid + it*256;
            int mm = e >> 3, kk = e & 7;
            int gm = m0 + mm;
            As[kk][mm] = (gm < Mr) ? A[(long long)gm*lda + k0 + kk] : 0.f;
        }
        #pragma unroll
        for (int it = 0; it < 4; it++) {
            int e = tid + it*256;
            if (TRB) {
                int nn = e >> 3, kk = e & 7;
                int gn = n0 + nn;
                Bs[kk][nn] = (gn < Nc) ? B[(long long)gn*ldb + k0 + kk] : 0.f;
            } else {
                int kk = e >> 7, nn = e & 127;
                int gn = n0 + nn;
                Bs[kk][nn] = (gn < Nc) ? B[(long long)(k0+kk)*ldb + gn] : 0.f;
            }
        }
        __syncthreads();
        #pragma unroll
        for (int kk = 0; kk < 8; kk++) {
            float a[8], bv[8];
            #pragma unroll
            for (int i = 0; i < 8; i++) a[i] = As[kk][ty*8 + i];
            #pragma unroll
            for (int j = 0; j < 8; j++) bv[j] = Bs[kk][tx*8 + j];
            #pragma unroll
            for (int i = 0; i < 8; i++)
                #pragma unroll
                for (int j = 0; j < 8; j++)
                    acc[i][j] = fmaf(a[i], bv[j], acc[i][j]);
        }
        __syncthreads();
    }

    #pragma unroll
    for (int i = 0; i < 8; i++) {
        int gm = m0 + ty*8 + i;
        if (gm >= Mr) continue;
        #pragma unroll
        for (int j = 0; j < 8; j++) {
            int gn = n0 + tx*8 + j;
            if (gn >= Nc) continue;
            float v = acc[i][j] * alpha;
            if (BIAS) v += bias[gn];
            if (RES)  v += R[(long long)gm*ldc + gn];
            if (RELU) v = fmaxf(v, 0.f);
            C[(long long)gm*ldc + gn] = v;
        }
    }
}

// ---------------- elementwise / reduction kernels ----------------

// h += pe[s,d] + t_embed[b,d]
__global__ void add_pe_k(float* __restrict__ h, const float* __restrict__ temb)
{
    long long idx = (long long)blockIdx.x * 256 + threadIdx.x;
    if (idx >= (long long)NTOK * CD) return;
    int d = (int)(idx & (CD-1));
    long long bs = idx >> 9;
    int s  = (int)(bs & (CS-1));
    int bb = (int)(bs >> 10);
    int i2 = d & ~1;
    float dv  = expf((float)i2 * (-9.210340371976184f / (float)CD)); // ln(10000)
    float ang = (float)s * dv;
    float pe  = (d & 1) ? cosf(ang) : sinf(ang);
    h[idx] += pe + temb[(long long)bb*CD + d];
}

// row softmax, generic ncols
__global__ void softmax_rows_k(float* __restrict__ X, int ncols)
{
    long long row = blockIdx.x;
    float* x = X + row * (long long)ncols;
    __shared__ float red[256];
    int tid = threadIdx.x;
    float m = -3.0e38f;
    for (int c = tid; c < ncols; c += 256) m = fmaxf(m, x[c]);
    red[tid] = m; __syncthreads();
    for (int off = 128; off > 0; off >>= 1) {
        if (tid < off) red[tid] = fmaxf(red[tid], red[tid+off]);
        __syncthreads();
    }
    float mx = red[0];
    __syncthreads();
    float s = 0.f;
    for (int c = tid; c < ncols; c += 256) { float e = expf(x[c]-mx); x[c] = e; s += e; }
    red[tid] = s; __syncthreads();
    for (int off = 128; off > 0; off >>= 1) {
        if (tid < off) red[tid] += red[tid+off];
        __syncthreads();
    }
    float inv = 1.f / red[0];
    for (int c = tid; c < ncols; c += 256) x[c] *= inv;
}

// in-place layernorm over rows of length 512
__global__ void layernorm512_k(float* __restrict__ X, const float* __restrict__ g,
                               const float* __restrict__ b)
{
    long long row = blockIdx.x;
    float* x = X + row * (long long)CD;
    __shared__ float red[256];
    int tid = threadIdx.x;
    float v0 = x[tid], v1 = x[tid+256];
    red[tid] = v0 + v1; __syncthreads();
    for (int off = 128; off > 0; off >>= 1) {
        if (tid < off) red[tid] += red[tid+off];
        __syncthreads();
    }
    float mu = red[0] * (1.f/512.f);
    __syncthreads();
    float d0 = v0 - mu, d1 = v1 - mu;
    red[tid] = d0*d0 + d1*d1; __syncthreads();
    for (int off = 128; off > 0; off >>= 1) {
        if (tid < off) red[tid] += red[tid+off];
        __syncthreads();
    }
    float var = red[0] * (1.f/512.f);
    float rs = 1.f / sqrtf(var + 1e-5f);
    x[tid]     = d0*rs*g[tid]     + b[tid];
    x[tid+256] = d1*rs*g[tid+256] + b[tid+256];
}

// p2[b,m] = sum_d Phi^2 ; kb[b,m] = 0.3*log(Size+1e-6) - 0.5*mean(Sig^2)
__global__ void bank_prep_k(const float* __restrict__ Phi, const float* __restrict__ Sig,
                            const float* __restrict__ Size,
                            float* __restrict__ p2, float* __restrict__ kb)
{
    int i = blockIdx.x * 256 + threadIdx.x;
    if (i >= CB*CM) return;
    const float* ph = Phi + (long long)i*CD;
    const float* sg = Sig + (long long)i*CD;
    float s = 0.f, s2 = 0.f;
    for (int d = 0; d < CD; d++) { s += ph[d]*ph[d]; s2 += sg[d]*sg[d]; }
    p2[i] = s;
    kb[i] = 0.3f * logf(Size[i] + 1e-6f) - 0.5f * (s2 * (1.f/(float)CD));
}

// Sdot[b,h,m,n] (already = dot*scale) -> scores = dot - dist2/512 + kb[b,n]
__global__ void bank_scores_k(float* __restrict__ Sdot, const float* __restrict__ phidot,
                              const float* __restrict__ p2, const float* __restrict__ kb)
{
    long long idx = (long long)blockIdx.x * 256 + threadIdx.x;
    if (idx >= (long long)CB*CH*CM*CM) return;
    int n = (int)(idx & (CM-1));
    long long t = idx >> 8;
    int m = (int)(t & (CM-1));
    long long t2 = t >> 8;          // b*H + h
    int bb = (int)(t2 >> 3);
    float d2 = p2[bb*CM + m] + p2[bb*CM + n]
             - 2.f * phidot[((long long)bb*CM + m)*CM + n];
    Sdot[idx] = Sdot[idx] - d2 * (1.f/(float)CD) + kb[bb*CM + n];
}

// per token: top-4 over 256 logits, softmax weights, gather Z, add h
__global__ void router_k(const float* __restrict__ logits, const float* __restrict__ h,
                         const float* __restrict__ Z, float* __restrict__ out)
{
    int row = blockIdx.x;          // b*S + s
    int bb  = row >> 10;
    const float* lg = logits + (long long)row * CM;
    __shared__ float sv[256];
    __shared__ float rv[256];
    __shared__ int   ri[256];
    __shared__ float topv[4];
    __shared__ int   topi[4];
    __shared__ float w[4];
    int tid = threadIdx.x;
    sv[tid] = lg[tid];
    __syncthreads();
    for (int kk = 0; kk < 4; kk++) {
        rv[tid] = sv[tid]; ri[tid] = tid;
        __syncthreads();
        for (int off = 128; off > 0; off >>= 1) {
            if (tid < off) {
                float v2 = rv[tid+off]; int i2 = ri[tid+off];
                if (v2 > rv[tid] || (v2 == rv[tid] && i2 < ri[tid])) { rv[tid] = v2; ri[tid] = i2; }
            }
            __syncthreads();
        }
        if (tid == 0) {
            topv[kk] = rv[0]; topi[kk] = ri[0];
            sv[ri[0]] = -3.0e38f;
        }
        __syncthreads();
    }
    if (tid == 0) {
        float mx = topv[0];
        float e0 = expf(topv[0]-mx), e1 = expf(topv[1]-mx),
              e2 = expf(topv[2]-mx), e3 = expf(topv[3]-mx);
        float inv = 1.f / (e0+e1+e2+e3);
        w[0]=e0*inv; w[1]=e1*inv; w[2]=e2*inv; w[3]=e3*inv;
    }
    __syncthreads();
    const float* hr = h + (long long)row*CD;
    float w0=w[0], w1=w[1], w2=w[2], w3=w[3];
    const float* z0 = Z + ((long long)bb*CM + topi[0])*CD;
    const float* z1 = Z + ((long long)bb*CM + topi[1])*CD;
    const float* z2 = Z + ((long long)bb*CM + topi[2])*CD;
    const float* z3 = Z + ((long long)bb*CM + topi[3])*CD;
    for (int d = tid; d < CD; d += 256)
        out[(long long)row*CD + d] = hr[d] + w0*z0[d] + w1*z1[d] + w2*z2[d] + w3*z3[d];
}

// ---------------- host side ----------------

enum GMode { G_PLAIN, G_BIAS, G_BIAS_RES, G_BIAS_RELU, G_TRANS };

static inline void gemm(GMode mode, const float* A, const float* Bm, float* C,
                        const float* bias, const float* Res,
                        int Mr, int Nc, int Kd, int lda, int ldb, int ldc,
                        int batches, int Hb,
                        long long sAb, long long sAh,
                        long long sBb, long long sBh,
                        long long sCb, long long sCh, float alpha)
{
    dim3 grid((Nc + 127)/128, (Mr + 127)/128, batches);
    switch (mode) {
    case G_PLAIN:
        gemm_k<false,false,false,false><<<grid,256>>>(A,Bm,C,bias,Res,Mr,Nc,Kd,lda,ldb,ldc,Hb,sAb,sAh,sBb,sBh,sCb,sCh,alpha); break;
    case G_BIAS:
        gemm_k<false,true ,false,false><<<grid,256>>>(A,Bm,C,bias,Res,Mr,Nc,Kd,lda,ldb,ldc,Hb,sAb,sAh,sBb,sBh,sCb,sCh,alpha); break;
    case G_BIAS_RES:
        gemm_k<false,true ,false,true ><<<grid,256>>>(A,Bm,C,bias,Res,Mr,Nc,Kd,lda,ldb,ldc,Hb,sAb,sAh,sBb,sBh,sCb,sCh,alpha); break;
    case G_BIAS_RELU:
        gemm_k<false,true ,true ,false><<<grid,256>>>(A,Bm,C,bias,Res,Mr,Nc,Kd,lda,ldb,ldc,Hb,sAb,sAh,sBb,sBh,sCb,sCh,alpha); break;
    case G_TRANS:
        gemm_k<true ,false,false,false><<<grid,256>>>(A,Bm,C,bias,Res,Mr,Nc,Kd,lda,ldb,ldc,Hb,sAb,sAh,sBb,sBh,sCb,sCh,alpha); break;
    }
}

extern "C" void kernel_launch(void* const* d_in, const int* in_sizes, int n_in,
                              void* d_out, int out_size)
{
    const float* x_t      = (const float*)d_in[0];
    const float* t_embed  = (const float*)d_in[1];
    const float* Phi      = (const float*)d_in[2];
    const float* Sig      = (const float*)d_in[3];
    const float* Size     = (const float*)d_in[4];
    /* d_in[5] = mask: all-True by construction, ignored */
    const float* Win      = (const float*)d_in[6];
    const float* b_in     = (const float*)d_in[7];
    const float* Wout     = (const float*)d_in[8];
    const float* b_out    = (const float*)d_in[9];
    const float* enc_Wqkv = (const float*)d_in[10];
    const float* enc_bqkv = (const float*)d_in[11];
    const float* enc_Wo   = (const float*)d_in[12];
    const float* enc_bo   = (const float*)d_in[13];
    const float* ln1_g    = (const float*)d_in[14];
    const float* ln1_b    = (const float*)d_in[15];
    const float* ln2_g    = (const float*)d_in[16];
    const float* ln2_b    = (const float*)d_in[17];
    const float* ff_W1    = (const float*)d_in[18];
    const float* ff_b1    = (const float*)d_in[19];
    const float* ff_W2    = (const float*)d_in[20];
    const float* ff_b2    = (const float*)d_in[21];
    const float* sa_Wq    = (const float*)d_in[22];
    const float* sa_Wk    = (const float*)d_in[23];
    const float* sa_Wv    = (const float*)d_in[24];
    const float* sa_Wo    = (const float*)d_in[25];
    const float* rt_Wq    = (const float*)d_in[26];

    float* sc = nullptr;
    cudaGetSymbolAddress((void**)&sc, g_scratch);
    float* h      = sc + O_H;
    float* qkv    = sc + O_QKV;
    float* scores = sc + O_SC;
    float* attno  = sc + O_AO;
    float* ff     = sc + O_FF;
    float* bq     = sc + O_BQ;
    float* bk     = sc + O_BK;
    float* bv     = sc + O_BV;
    float* zc     = sc + O_ZC;
    float* Zb     = sc + O_Z;
    float* phidot = sc + O_PD;
    float* p2     = sc + O_P2;
    float* kb     = sc + O_KB;
    float* hq     = sc + O_HQ;
    float* lgts   = sc + O_LG;
    float* routed = sc + O_RT;

    const float scaleDH = 0.125f;                 // 1/sqrt(64)
    const float scaleD  = 0.04419417382415922f;   // 1/sqrt(512)

    // ---- input proj + PE + t_embed ----
    gemm(G_BIAS, x_t, Win, h, b_in, nullptr,
         NTOK, CD, CIN, CIN, CD, CD, 1, 1, 0,0,0,0,0,0, 1.f);
    add_pe_k<<<(NTOK*(long long)CD + 255)/256, 256>>>(h, t_embed);

    // ---- encoder layers ----
    for (int l = 0; l < CL; l++) {
        const float* Wqkv = enc_Wqkv + (long long)l*CD*3*CD;
        const float* bqkv = enc_bqkv + (long long)l*3*CD;
        const float* Wo   = enc_Wo   + (long long)l*CD*CD;
        const float* bo   = enc_bo   + (long long)l*CD;

        gemm(G_BIAS, h, Wqkv, qkv, bqkv, nullptr,
             NTOK, 3*CD, CD, CD, 3*CD, 3*CD, 1, 1, 0,0,0,0,0,0, 1.f);

        // scores = Q @ K^T * scale, batched over (b,h)
        gemm(G_TRANS, qkv, qkv + CD, scores, nullptr, nullptr,
             CS, CS, CDH, 3*CD, 3*CD, CS,
             CB*CH, CH,
             (long long)CS*3*CD, CDH,
             (long long)CS*3*CD, CDH,
             (long long)CH*CS*CS, (long long)CS*CS, scaleDH);

        softmax_rows_k<<<CB*CH*CS, 256>>>(scores, CS);

        // O = P @ V, batched, written straight into head-concat layout
        gemm(G_PLAIN, scores, qkv + 2*CD, attno, nullptr, nullptr,
             CS, CDH, CS, CS, 3*CD, CD,
             CB*CH, CH,
             (long long)CH*CS*CS, (long long)CS*CS,
             (long long)CS*3*CD, CDH,
             (long long)CS*CD, CDH, 1.f);

        // h = h + O @ Wo + bo, then LN1
        gemm(G_BIAS_RES, attno, Wo, h, bo, h,
             NTOK, CD, CD, CD, CD, CD, 1, 1, 0,0,0,0,0,0, 1.f);
        layernorm512_k<<<NTOK, 256>>>(h, ln1_g + (long long)l*CD, ln1_b + (long long)l*CD);

        // FF
        gemm(G_BIAS_RELU, h, ff_W1 + (long long)l*CD*CDFF, ff,
             ff_b1 + (long long)l*CDFF, nullptr,
             NTOK, CDFF, CD, CD, CDFF, CDFF, 1, 1, 0,0,0,0,0,0, 1.f);
        gemm(G_BIAS_RES, ff, ff_W2 + (long long)l*CDFF*CD, h,
             ff_b2 + (long long)l*CD, h,
             NTOK, CD, CDFF, CDFF, CD, CD, 1, 1, 0,0,0,0,0,0, 1.f);
        layernorm512_k<<<NTOK, 256>>>(h, ln2_g + (long long)l*CD, ln2_b + (long long)l*CD);
    }

    // ---- SetBankAttention ----
    gemm(G_PLAIN, Phi, sa_Wq, bq, nullptr, nullptr, CB*CM, CD, CD, CD, CD, CD, 1,1,0,0,0,0,0,0, 1.f);
    gemm(G_PLAIN, Phi, sa_Wk, bk, nullptr, nullptr, CB*CM, CD, CD, CD, CD, CD, 1,1,0,0,0,0,0,0, 1.f);
    gemm(G_PLAIN, Phi, sa_Wv, bv, nullptr, nullptr, CB*CM, CD, CD, CD, CD, CD, 1,1,0,0,0,0,0,0, 1.f);

    // Phi @ Phi^T per batch
    gemm(G_TRANS, Phi, Phi, phidot, nullptr, nullptr,
         CM, CM, CD, CD, CD, CM,
         CB, 1,
         (long long)CM*CD, 0, (long long)CM*CD, 0,
         (long long)CM*CM, 0, 1.f);

    // dot = Q @ K^T * scale per (b,h)  (reuse attn score buffer)
    gemm(G_TRANS, bq, bk, scores, nullptr, nullptr,
         CM, CM, CDH, CD, CD, CM,
         CB*CH, CH,
         (long long)CM*CD, CDH,
         (long long)CM*CD, CDH,
         (long long)CH*CM*CM, (long long)CM*CM, scaleDH);

    bank_prep_k<<<(CB*CM + 255)/256, 256>>>(Phi, Sig, Size, p2, kb);
    bank_scores_k<<<((long long)CB*CH*CM*CM + 255)/256, 256>>>(scores, phidot, p2, kb);
    softmax_rows_k<<<CB*CH*CM, 256>>>(scores, CM);

    // Zc = A @ V per (b,h), into head-concat layout
    gemm(G_PLAIN, scores, bv, zc, nullptr, nullptr,
         CM, CDH, CM, CM, CD, CD,
         CB*CH, CH,
         (long long)CH*CM*CM, (long long)CM*CM,
         (long long)CM*CD, CDH,
         (long long)CM*CD, CDH, 1.f);

    gemm(G_PLAIN, zc, sa_Wo, Zb, nullptr, nullptr, CB*CM, CD, CD, CD, CD, CD, 1,1,0,0,0,0,0,0, 1.f);

    // ---- router ----
    gemm(G_PLAIN, h, rt_Wq, hq, nullptr, nullptr, NTOK, CD, CD, CD, CD, CD, 1,1,0,0,0,0,0,0, 1.f);
    gemm(G_TRANS, hq, Phi, lgts, nullptr, nullptr,
         CS, CM, CD, CD, CD, CM,
         CB, 1,
         (long long)CS*CD, 0, (long long)CM*CD, 0,
         (long long)CS*CM, 0, scaleD);

    router_k<<<NTOK, 256>>>(lgts, h, Zb, routed);

    // ---- output proj ----
    gemm(G_BIAS, routed, Wout, (float*)d_out, b_out, nullptr,
         NTOK, CIN, CD, CD, CIN, CIN, 1, 1, 0,0,0,0,0,0, 1.f);
}

// round 3
// speedup vs baseline: 1.2568x; 1.2568x over previous
#include <cuda_runtime.h>
#include <math.h>
#include <stdint.h>

// ---------------- problem constants ----------------
#define CB   8
#define CS   1024
#define CIN  256
#define CD   512
#define CH   8
#define CL   4
#define CM   256
#define CDFF 2048
#define CDH  64
#define NTOK (CB*CS)

// ---------------- scratch layout (floats) ----------------
constexpr long long O_H    = 0,                 S_H    = (long long)NTOK*CD;
constexpr long long O_QKV  = O_H + S_H,         S_QKV  = (long long)NTOK*3*CD;
constexpr long long O_SC   = O_QKV + S_QKV,     S_SC   = (long long)CB*CH*CS*CS;
constexpr long long O_AO   = O_SC + S_SC,       S_AO   = (long long)NTOK*CD;
constexpr long long O_FF   = O_AO + S_AO,       S_FF   = (long long)NTOK*CDFF;
constexpr long long S_BNK  = (long long)CB*CM*CD;
constexpr long long O_BQ   = O_FF + S_FF;
constexpr long long O_BK   = O_BQ + S_BNK;
constexpr long long O_BV   = O_BK + S_BNK;
constexpr long long O_ZC   = O_BV + S_BNK;
constexpr long long O_Z    = O_ZC + S_BNK;
constexpr long long O_PD   = O_Z + S_BNK,       S_PD   = (long long)CB*CM*CM;
constexpr long long O_P2   = O_PD + S_PD;
constexpr long long O_KB   = O_P2 + CB*CM;
constexpr long long O_HQ   = O_KB + CB*CM,      S_HQ   = (long long)NTOK*CD;
constexpr long long O_LG   = O_HQ + S_HQ,       S_LG   = (long long)NTOK*CM;
constexpr long long O_RT   = O_LG + S_LG,       S_RT   = (long long)NTOK*CD;
constexpr long long TOTAL_SCRATCH = O_RT + S_RT;

__device__ float g_scratch[TOTAL_SCRATCH];

// ---------------- tf32 helpers ----------------
__device__ __forceinline__ void split_tf32(float x, uint32_t &hi, uint32_t &lo)
{
    uint32_t h;
    asm("cvt.rna.tf32.f32 %0, %1;" : "=r"(h) : "f"(x));
    float hf = __uint_as_float(h);
    uint32_t l;
    asm("cvt.rna.tf32.f32 %0, %1;" : "=r"(l) : "f"(x - hf));
    hi = h; lo = l;
}

__device__ __forceinline__ void mma_tf32(float* c, const uint32_t* a, const uint32_t* b)
{
    asm volatile(
        "mma.sync.aligned.m16n8k8.row.col.f32.tf32.tf32.f32 "
        "{%0,%1,%2,%3}, {%4,%5,%6,%7}, {%8,%9}, {%0,%1,%2,%3};\n"
        : "+f"(c[0]), "+f"(c[1]), "+f"(c[2]), "+f"(c[3])
        : "r"(a[0]), "r"(a[1]), "r"(a[2]), "r"(a[3]),
          "r"(b[0]), "r"(b[1]));
}

// ---------------- tensor-core 3xTF32 strided-batched GEMM ----------------
// C[m,n] = alpha * sum_k A[m,k] * (TRB ? B[n,k] : B[k,n]) (+bias[n]) (+Res) (relu)
// BM=128, BN=128, BK=16. 256 threads = 8 warps (2 x 4), warp tile 64x32.
// Requires Kd % 16 == 0, Nc % 8 == 0 (all call sites satisfy this).
template<bool TRB, bool BIAS, bool RELU, bool RES>
__global__ __launch_bounds__(256)
void gemm_tc(const float* __restrict__ A, const float* __restrict__ B,
             float* __restrict__ C, const float* __restrict__ bias,
             const float* __restrict__ Res,
             int Mr, int Nc, int Kd, int lda, int ldb, int ldc,
             int Hb,
             long long sAb, long long sAh, long long sBb, long long sBh,
             long long sCb, long long sCh, float alpha)
{
    constexpr int SMA = 136;   // 128 + 8 pad -> conflict-free frag loads
    __shared__ float Ahs[16*SMA], Als[16*SMA], Bhs[16*SMA], Bls[16*SMA];

    int z = blockIdx.z;
    int zb = z / Hb, zh = z - zb*Hb;
    A += (long long)zb*sAb + (long long)zh*sAh;
    B += (long long)zb*sBb + (long long)zh*sBh;
    C += (long long)zb*sCb + (long long)zh*sCh;
    const float* Rp = RES ? (Res + (long long)zb*sCb + (long long)zh*sCh) : nullptr;

    const int m0 = blockIdx.y * 128;
    const int n0 = blockIdx.x * 128;
    const int tid = threadIdx.x;
    const int lane = tid & 31, warp = tid >> 5;
    const int wm = (warp >> 2) * 64;
    const int wn = (warp & 3) * 32;
    const int g = lane >> 2, kq = lane & 3;

    float acc[4][4][4];
    #pragma unroll
    for (int i = 0; i < 4; i++)
        #pragma unroll
        for (int j = 0; j < 4; j++)
            #pragma unroll
            for (int r = 0; r < 4; r++) acc[i][j][r] = 0.f;

    // staging indices
    const int amm = tid >> 1, akt = (tid & 1) << 3;            // A (and TRB B)
    const int bkk = tid >> 4, bnn0 = (tid & 15) << 3;          // non-TRB B

    float va[8], vb[8];

    // ---- prefetch k0 = 0 ----
    {
        int gm = m0 + amm;
        if (gm < Mr) {
            const float* p = A + (long long)gm*lda + akt;
            float4 u0 = *(const float4*)p;
            float4 u1 = *(const float4*)(p + 4);
            va[0]=u0.x; va[1]=u0.y; va[2]=u0.z; va[3]=u0.w;
            va[4]=u1.x; va[5]=u1.y; va[6]=u1.z; va[7]=u1.w;
        } else {
            #pragma unroll
            for (int u = 0; u < 8; u++) va[u] = 0.f;
        }
        if (TRB) {
            int gn = n0 + amm;
            if (gn < Nc) {
                const float* p = B + (long long)gn*ldb + akt;
                float4 u0 = *(const float4*)p;
                float4 u1 = *(const float4*)(p + 4);
                vb[0]=u0.x; vb[1]=u0.y; vb[2]=u0.z; vb[3]=u0.w;
                vb[4]=u1.x; vb[5]=u1.y; vb[6]=u1.z; vb[7]=u1.w;
            } else {
                #pragma unroll
                for (int u = 0; u < 8; u++) vb[u] = 0.f;
            }
        } else {
            int gn0 = n0 + bnn0;
            if (gn0 + 7 < Nc) {
                const float* p = B + (long long)bkk*ldb + gn0;
                float4 u0 = *(const float4*)p;
                float4 u1 = *(const float4*)(p + 4);
                vb[0]=u0.x; vb[1]=u0.y; vb[2]=u0.z; vb[3]=u0.w;
                vb[4]=u1.x; vb[5]=u1.y; vb[6]=u1.z; vb[7]=u1.w;
            } else {
                #pragma unroll
                for (int u = 0; u < 8; u++) vb[u] = 0.f;
            }
        }
    }

    for (int k0 = 0; k0 < Kd; k0 += 16) {
        __syncthreads();   // previous compute finished reading smem
        // store staged regs -> smem with tf32 hi/lo split
        #pragma unroll
        for (int u = 0; u < 8; u++) {
            uint32_t h, l;
            split_tf32(va[u], h, l);
            Ahs[(akt + u)*SMA + amm] = __uint_as_float(h);
            Als[(akt + u)*SMA + amm] = __uint_as_float(l);
        }
        if (TRB) {
            #pragma unroll
            for (int u = 0; u < 8; u++) {
                uint32_t h, l;
                split_tf32(vb[u], h, l);
                Bhs[(akt + u)*SMA + amm] = __uint_as_float(h);
                Bls[(akt + u)*SMA + amm] = __uint_as_float(l);
            }
        } else {
            #pragma unroll
            for (int u = 0; u < 8; u++) {
                uint32_t h, l;
                split_tf32(vb[u], h, l);
                Bhs[bkk*SMA + bnn0 + u] = __uint_as_float(h);
                Bls[bkk*SMA + bnn0 + u] = __uint_as_float(l);
            }
        }
        __syncthreads();

        // prefetch next tile (global loads overlap compute)
        if (k0 + 16 < Kd) {
            int kn = k0 + 16;
            int gm = m0 + amm;
            if (gm < Mr) {
                const float* p = A + (long long)gm*lda + kn + akt;
                float4 u0 = *(const float4*)p;
                float4 u1 = *(const float4*)(p + 4);
                va[0]=u0.x; va[1]=u0.y; va[2]=u0.z; va[3]=u0.w;
                va[4]=u1.x; va[5]=u1.y; va[6]=u1.z; va[7]=u1.w;
            } else {
                #pragma unroll
                for (int u = 0; u < 8; u++) va[u] = 0.f;
            }
            if (TRB) {
                int gn = n0 + amm;
                if (gn < Nc) {
                    const float* p = B + (long long)gn*ldb + kn + akt;
                    float4 u0 = *(const float4*)p;
                    float4 u1 = *(const float4*)(p + 4);
                    vb[0]=u0.x; vb[1]=u0.y; vb[2]=u0.z; vb[3]=u0.w;
                    vb[4]=u1.x; vb[5]=u1.y; vb[6]=u1.z; vb[7]=u1.w;
                } else {
                    #pragma unroll
                    for (int u = 0; u < 8; u++) vb[u] = 0.f;
                }
            } else {
                int gn0 = n0 + bnn0;
                if (gn0 + 7 < Nc) {
                    const float* p = B + (long long)(kn + bkk)*ldb + gn0;
                    float4 u0 = *(const float4*)p;
                    float4 u1 = *(const float4*)(p + 4);
                    vb[0]=u0.x; vb[1]=u0.y; vb[2]=u0.z; vb[3]=u0.w;
                    vb[4]=u1.x; vb[5]=u1.y; vb[6]=u1.z; vb[7]=u1.w;
                } else {
                    #pragma unroll
                    for (int u = 0; u < 8; u++) vb[u] = 0.f;
                }
            }
        }

        // ---- compute: 2 ksteps of 8 ----
        #pragma unroll
        for (int ks = 0; ks < 16; ks += 8) {
            uint32_t ah[4][4], al[4][4], bh[4][2], bl[4][2];
            #pragma unroll
            for (int i = 0; i < 4; i++) {
                int base = (ks + kq)*SMA + wm + 16*i + g;
                ah[i][0] = __float_as_uint(Ahs[base]);
                ah[i][1] = __float_as_uint(Ahs[base + 8]);
                ah[i][2] = __float_as_uint(Ahs[base + 4*SMA]);
                ah[i][3] = __float_as_uint(Ahs[base + 4*SMA + 8]);
                al[i][0] = __float_as_uint(Als[base]);
                al[i][1] = __float_as_uint(Als[base + 8]);
                al[i][2] = __float_as_uint(Als[base + 4*SMA]);
                al[i][3] = __float_as_uint(Als[base + 4*SMA + 8]);
            }
            #pragma unroll
            for (int j = 0; j < 4; j++) {
                int cb = (ks + kq)*SMA + wn + 8*j + g;
                bh[j][0] = __float_as_uint(Bhs[cb]);
                bh[j][1] = __float_as_uint(Bhs[cb + 4*SMA]);
                bl[j][0] = __float_as_uint(Bls[cb]);
                bl[j][1] = __float_as_uint(Bls[cb + 4*SMA]);
            }
            #pragma unroll
            for (int i = 0; i < 4; i++)
                #pragma unroll
                for (int j = 0; j < 4; j++) {
                    mma_tf32(acc[i][j], ah[i], bl[j]);
                    mma_tf32(acc[i][j], al[i], bh[j]);
                    mma_tf32(acc[i][j], ah[i], bh[j]);
                }
        }
    }

    // ---- epilogue ----
    #pragma unroll
    for (int i = 0; i < 4; i++) {
        int r0 = m0 + wm + 16*i + g;
        int r1 = r0 + 8;
        #pragma unroll
        for (int j = 0; j < 4; j++) {
            int col = n0 + wn + 8*j + 2*kq;
            if (col >= Nc) continue;
            float b0 = 0.f, b1 = 0.f;
            if (BIAS) { b0 = bias[col]; b1 = bias[col + 1]; }
            if (r0 < Mr) {
                float v0 = acc[i][j][0]*alpha + b0;
                float v1 = acc[i][j][1]*alpha + b1;
                if (RES) {
                    const float* rp = Rp + (long long)r0*ldc + col;
                    v0 += rp[0]; v1 += rp[1];
                }
                if (RELU) { v0 = fmaxf(v0, 0.f); v1 = fmaxf(v1, 0.f); }
                *(float2*)&C[(long long)r0*ldc + col] = make_float2(v0, v1);
            }
            if (r1 < Mr) {
                float v0 = acc[i][j][2]*alpha + b0;
                float v1 = acc[i][j][3]*alpha + b1;
                if (RES) {
                    const float* rp = Rp + (long long)r1*ldc + col;
                    v0 += rp[0]; v1 += rp[1];
                }
                if (RELU) { v0 = fmaxf(v0, 0.f); v1 = fmaxf(v1, 0.f); }
                *(float2*)&C[(long long)r1*ldc + col] = make_float2(v0, v1);
            }
        }
    }
}

// ---------------- elementwise / reduction kernels ----------------

__global__ void add_pe_k(float* __restrict__ h, const float* __restrict__ temb)
{
    long long idx = (long long)blockIdx.x * 256 + threadIdx.x;
    if (idx >= (long long)NTOK * CD) return;
    int d = (int)(idx & (CD-1));
    long long bs = idx >> 9;
    int s  = (int)(bs & (CS-1));
    int bb = (int)(bs >> 10);
    int i2 = d & ~1;
    float dv  = expf((float)i2 * (-9.210340371976184f / (float)CD));
    float ang = (float)s * dv;
    float pe  = (d & 1) ? cosf(ang) : sinf(ang);
    h[idx] += pe + temb[(long long)bb*CD + d];
}

// register-resident softmax over 1024 cols (256 thr x float4)
__global__ __launch_bounds__(256)
void softmax1024_k(float* __restrict__ X)
{
    long long row = blockIdx.x;
    float4* x = (float4*)(X + row * 1024);
    int tid = threadIdx.x;
    float4 v = x[tid];
    __shared__ float red[8];

    float m = fmaxf(fmaxf(v.x, v.y), fmaxf(v.z, v.w));
    #pragma unroll
    for (int off = 16; off > 0; off >>= 1)
        m = fmaxf(m, __shfl_xor_sync(0xffffffffu, m, off));
    if ((tid & 31) == 0) red[tid >> 5] = m;
    __syncthreads();
    m = red[0];
    #pragma unroll
    for (int w = 1; w < 8; w++) m = fmaxf(m, red[w]);

    v.x = __expf(v.x - m); v.y = __expf(v.y - m);
    v.z = __expf(v.z - m); v.w = __expf(v.w - m);
    float s = v.x + v.y + v.z + v.w;
    #pragma unroll
    for (int off = 16; off > 0; off >>= 1)
        s += __shfl_xor_sync(0xffffffffu, s, off);
    __syncthreads();
    if ((tid & 31) == 0) red[tid >> 5] = s;
    __syncthreads();
    s = red[0];
    #pragma unroll
    for (int w = 1; w < 8; w++) s += red[w];

    float inv = 1.f / s;
    v.x *= inv; v.y *= inv; v.z *= inv; v.w *= inv;
    x[tid] = v;
}

// generic row softmax (used for bank, 256 cols)
__global__ void softmax_rows_k(float* __restrict__ X, int ncols)
{
    long long row = blockIdx.x;
    float* x = X + row * (long long)ncols;
    __shared__ float red[256];
    int tid = threadIdx.x;
    float m = -3.0e38f;
    for (int c = tid; c < ncols; c += 256) m = fmaxf(m, x[c]);
    red[tid] = m; __syncthreads();
    for (int off = 128; off > 0; off >>= 1) {
        if (tid < off) red[tid] = fmaxf(red[tid], red[tid+off]);
        __syncthreads();
    }
    float mx = red[0];
    __syncthreads();
    float s = 0.f;
    for (int c = tid; c < ncols; c += 256) { float e = __expf(x[c]-mx); x[c] = e; s += e; }
    red[tid] = s; __syncthreads();
    for (int off = 128; off > 0; off >>= 1) {
        if (tid < off) red[tid] += red[tid+off];
        __syncthreads();
    }
    float inv = 1.f / red[0];
    for (int c = tid; c < ncols; c += 256) x[c] *= inv;
}

__global__ void layernorm512_k(float* __restrict__ X, const float* __restrict__ g,
                               const float* __restrict__ b)
{
    long long row = blockIdx.x;
    float* x = X + row * (long long)CD;
    __shared__ float red[256];
    int tid = threadIdx.x;
    float v0 = x[tid], v1 = x[tid+256];
    red[tid] = v0 + v1; __syncthreads();
    for (int off = 128; off > 0; off >>= 1) {
        if (tid < off) red[tid] += red[tid+off];
        __syncthreads();
    }
    float mu = red[0] * (1.f/512.f);
    __syncthreads();
    float d0 = v0 - mu, d1 = v1 - mu;
    red[tid] = d0*d0 + d1*d1; __syncthreads();
    for (int off = 128; off > 0; off >>= 1) {
        if (tid < off) red[tid] += red[tid+off];
        __syncthreads();
    }
    float var = red[0] * (1.f/512.f);
    float rs = 1.f / sqrtf(var + 1e-5f);
    x[tid]     = d0*rs*g[tid]     + b[tid];
    x[tid+256] = d1*rs*g[tid+256] + b[tid+256];
}

__global__ void bank_prep_k(const float* __restrict__ Phi, const float* __restrict__ Sig,
                            const float* __restrict__ Size,
                            float* __restrict__ p2, float* __restrict__ kb)
{
    int i = blockIdx.x * 256 + threadIdx.x;
    if (i >= CB*CM) return;
    const float* ph = Phi + (long long)i*CD;
    const float* sg = Sig + (long long)i*CD;
    float s = 0.f, s2 = 0.f;
    for (int d = 0; d < CD; d++) { s += ph[d]*ph[d]; s2 += sg[d]*sg[d]; }
    p2[i] = s;
    kb[i] = 0.3f * logf(Size[i] + 1e-6f) - 0.5f * (s2 * (1.f/(float)CD));
}

__global__ void bank_scores_k(float* __restrict__ Sdot, const float* __restrict__ phidot,
                              const float* __restrict__ p2, const float* __restrict__ kb)
{
    long long idx = (long long)blockIdx.x * 256 + threadIdx.x;
    if (idx >= (long long)CB*CH*CM*CM) return;
    int n = (int)(idx & (CM-1));
    long long t = idx >> 8;
    int m = (int)(t & (CM-1));
    long long t2 = t >> 8;
    int bb = (int)(t2 >> 3);
    float d2 = p2[bb*CM + m] + p2[bb*CM + n]
             - 2.f * phidot[((long long)bb*CM + m)*CM + n];
    Sdot[idx] = Sdot[idx] - d2 * (1.f/(float)CD) + kb[bb*CM + n];
}

__global__ void router_k(const float* __restrict__ logits, const float* __restrict__ h,
                         const float* __restrict__ Z, float* __restrict__ out)
{
    int row = blockIdx.x;
    int bb  = row >> 10;
    const float* lg = logits + (long long)row * CM;
    __shared__ float sv[256];
    __shared__ float rv[256];
    __shared__ int   ri[256];
    __shared__ float topv[4];
    __shared__ int   topi[4];
    __shared__ float w[4];
    int tid = threadIdx.x;
    sv[tid] = lg[tid];
    __syncthreads();
    for (int kk = 0; kk < 4; kk++) {
        rv[tid] = sv[tid]; ri[tid] = tid;
        __syncthreads();
        for (int off = 128; off > 0; off >>= 1) {
            if (tid < off) {
                float v2 = rv[tid+off]; int i2 = ri[tid+off];
                if (v2 > rv[tid] || (v2 == rv[tid] && i2 < ri[tid])) { rv[tid] = v2; ri[tid] = i2; }
            }
            __syncthreads();
        }
        if (tid == 0) {
            topv[kk] = rv[0]; topi[kk] = ri[0];
            sv[ri[0]] = -3.0e38f;
        }
        __syncthreads();
    }
    if (tid == 0) {
        float mx = topv[0];
        float e0 = __expf(topv[0]-mx), e1 = __expf(topv[1]-mx),
              e2 = __expf(topv[2]-mx), e3 = __expf(topv[3]-mx);
        float inv = 1.f / (e0+e1+e2+e3);
        w[0]=e0*inv; w[1]=e1*inv; w[2]=e2*inv; w[3]=e3*inv;
    }
    __syncthreads();
    const float* hr = h + (long long)row*CD;
    float w0=w[0], w1=w[1], w2=w[2], w3=w[3];
    const float* z0 = Z + ((long long)bb*CM + topi[0])*CD;
    const float* z1 = Z + ((long long)bb*CM + topi[1])*CD;
    const float* z2 = Z + ((long long)bb*CM + topi[2])*CD;
    const float* z3 = Z + ((long long)bb*CM + topi[3])*CD;
    for (int d = tid; d < CD; d += 256)
        out[(long long)row*CD + d] = hr[d] + w0*z0[d] + w1*z1[d] + w2*z2[d] + w3*z3[d];
}

// ---------------- host side ----------------

enum GMode { G_PLAIN, G_BIAS, G_BIAS_RES, G_BIAS_RELU, G_TRANS };

static inline void gemm(GMode mode, const float* A, const float* Bm, float* C,
                        const float* bias, const float* Res,
                        int Mr, int Nc, int Kd, int lda, int ldb, int ldc,
                        int batches, int Hb,
                        long long sAb, long long sAh,
                        long long sBb, long long sBh,
                        long long sCb, long long sCh, float alpha)
{
    dim3 grid((Nc + 127)/128, (Mr + 127)/128, batches);
    switch (mode) {
    case G_PLAIN:
        gemm_tc<false,false,false,false><<<grid,256>>>(A,Bm,C,bias,Res,Mr,Nc,Kd,lda,ldb,ldc,Hb,sAb,sAh,sBb,sBh,sCb,sCh,alpha); break;
    case G_BIAS:
        gemm_tc<false,true ,false,false><<<grid,256>>>(A,Bm,C,bias,Res,Mr,Nc,Kd,lda,ldb,ldc,Hb,sAb,sAh,sBb,sBh,sCb,sCh,alpha); break;
    case G_BIAS_RES:
        gemm_tc<false,true ,false,true ><<<grid,256>>>(A,Bm,C,bias,Res,Mr,Nc,Kd,lda,ldb,ldc,Hb,sAb,sAh,sBb,sBh,sCb,sCh,alpha); break;
    case G_BIAS_RELU:
        gemm_tc<false,true ,true ,false><<<grid,256>>>(A,Bm,C,bias,Res,Mr,Nc,Kd,lda,ldb,ldc,Hb,sAb,sAh,sBb,sBh,sCb,sCh,alpha); break;
    case G_TRANS:
        gemm_tc<true ,false,false,false><<<grid,256>>>(A,Bm,C,bias,Res,Mr,Nc,Kd,lda,ldb,ldc,Hb,sAb,sAh,sBb,sBh,sCb,sCh,alpha); break;
    }
}

extern "C" void kernel_launch(void* const* d_in, const int* in_sizes, int n_in,
                              void* d_out, int out_size)
{
    const float* x_t      = (const float*)d_in[0];
    const float* t_embed  = (const float*)d_in[1];
    const float* Phi      = (const float*)d_in[2];
    const float* Sig      = (const float*)d_in[3];
    const float* Size     = (const float*)d_in[4];
    /* d_in[5] = mask: all-True, ignored */
    const float* Win      = (const float*)d_in[6];
    const float* b_in     = (const float*)d_in[7];
    const float* Wout     = (const float*)d_in[8];
    const float* b_out    = (const float*)d_in[9];
    const float* enc_Wqkv = (const float*)d_in[10];
    const float* enc_bqkv = (const float*)d_in[11];
    const float* enc_Wo   = (const float*)d_in[12];
    const float* enc_bo   = (const float*)d_in[13];
    const float* ln1_g    = (const float*)d_in[14];
    const float* ln1_b    = (const float*)d_in[15];
    const float* ln2_g    = (const float*)d_in[16];
    const float* ln2_b    = (const float*)d_in[17];
    const float* ff_W1    = (const float*)d_in[18];
    const float* ff_b1    = (const float*)d_in[19];
    const float* ff_W2    = (const float*)d_in[20];
    const float* ff_b2    = (const float*)d_in[21];
    const float* sa_Wq    = (const float*)d_in[22];
    const float* sa_Wk    = (const float*)d_in[23];
    const float* sa_Wv    = (const float*)d_in[24];
    const float* sa_Wo    = (const float*)d_in[25];
    const float* rt_Wq    = (const float*)d_in[26];

    float* sc = nullptr;
    cudaGetSymbolAddress((void**)&sc, g_scratch);
    float* h      = sc + O_H;
    float* qkv    = sc + O_QKV;
    float* scores = sc + O_SC;
    float* attno  = sc + O_AO;
    float* ff     = sc + O_FF;
    float* bq     = sc + O_BQ;
    float* bk     = sc + O_BK;
    float* bv     = sc + O_BV;
    float* zc     = sc + O_ZC;
    float* Zb     = sc + O_Z;
    float* phidot = sc + O_PD;
    float* p2     = sc + O_P2;
    float* kb     = sc + O_KB;
    float* hq     = sc + O_HQ;
    float* lgts   = sc + O_LG;
    float* routed = sc + O_RT;

    const float scaleDH = 0.125f;
    const float scaleD  = 0.04419417382415922f;

    // ---- input proj + PE + t_embed ----
    gemm(G_BIAS, x_t, Win, h, b_in, nullptr,
         NTOK, CD, CIN, CIN, CD, CD, 1, 1, 0,0,0,0,0,0, 1.f);
    add_pe_k<<<(NTOK*(long long)CD + 255)/256, 256>>>(h, t_embed);

    // ---- encoder layers ----
    for (int l = 0; l < CL; l++) {
        const float* Wqkv = enc_Wqkv + (long long)l*CD*3*CD;
        const float* bqkv = enc_bqkv + (long long)l*3*CD;
        const float* Wo   = enc_Wo   + (long long)l*CD*CD;
        const float* bo   = enc_bo   + (long long)l*CD;

        gemm(G_BIAS, h, Wqkv, qkv, bqkv, nullptr,
             NTOK, 3*CD, CD, CD, 3*CD, 3*CD, 1, 1, 0,0,0,0,0,0, 1.f);

        gemm(G_TRANS, qkv, qkv + CD, scores, nullptr, nullptr,
             CS, CS, CDH, 3*CD, 3*CD, CS,
             CB*CH, CH,
             (long long)CS*3*CD, CDH,
             (long long)CS*3*CD, CDH,
             (long long)CH*CS*CS, (long long)CS*CS, scaleDH);

        softmax1024_k<<<CB*CH*CS, 256>>>(scores);

        gemm(G_PLAIN, scores, qkv + 2*CD, attno, nullptr, nullptr,
             CS, CDH, CS, CS, 3*CD, CD,
             CB*CH, CH,
             (long long)CH*CS*CS, (long long)CS*CS,
             (long long)CS*3*CD, CDH,
             (long long)CS*CD, CDH, 1.f);

        gemm(G_BIAS_RES, attno, Wo, h, bo, h,
             NTOK, CD, CD, CD, CD, CD, 1, 1, 0,0,0,0,0,0, 1.f);
        layernorm512_k<<<NTOK, 256>>>(h, ln1_g + (long long)l*CD, ln1_b + (long long)l*CD);

        gemm(G_BIAS_RELU, h, ff_W1 + (long long)l*CD*CDFF, ff,
             ff_b1 + (long long)l*CDFF, nullptr,
             NTOK, CDFF, CD, CD, CDFF, CDFF, 1, 1, 0,0,0,0,0,0, 1.f);
        gemm(G_BIAS_RES, ff, ff_W2 + (long long)l*CDFF*CD, h,
             ff_b2 + (long long)l*CD, h,
             NTOK, CD, CDFF, CDFF, CD, CD, 1, 1, 0,0,0,0,0,0, 1.f);
        layernorm512_k<<<NTOK, 256>>>(h, ln2_g + (long long)l*CD, ln2_b + (long long)l*CD);
    }

    // ---- SetBankAttention ----
    gemm(G_PLAIN, Phi, sa_Wq, bq, nullptr, nullptr, CB*CM, CD, CD, CD, CD, CD, 1,1,0,0,0,0,0,0, 1.f);
    gemm(G_PLAIN, Phi, sa_Wk, bk, nullptr, nullptr, CB*CM, CD, CD, CD, CD, CD, 1,1,0,0,0,0,0,0, 1.f);
    gemm(G_PLAIN, Phi, sa_Wv, bv, nullptr, nullptr, CB*CM, CD, CD, CD, CD, CD, 1,1,0,0,0,0,0,0, 1.f);

    gemm(G_TRANS, Phi, Phi, phidot, nullptr, nullptr,
         CM, CM, CD, CD, CD, CM,
         CB, 1,
         (long long)CM*CD, 0, (long long)CM*CD, 0,
         (long long)CM*CM, 0, 1.f);

    gemm(G_TRANS, bq, bk, scores, nullptr, nullptr,
         CM, CM, CDH, CD, CD, CM,
         CB*CH, CH,
         (long long)CM*CD, CDH,
         (long long)CM*CD, CDH,
         (long long)CH*CM*CM, (long long)CM*CM, scaleDH);

    bank_prep_k<<<(CB*CM + 255)/256, 256>>>(Phi, Sig, Size, p2, kb);
    bank_scores_k<<<((long long)CB*CH*CM*CM + 255)/256, 256>>>(scores, phidot, p2, kb);
    softmax_rows_k<<<CB*CH*CM, 256>>>(scores, CM);

    gemm(G_PLAIN, scores, bv, zc, nullptr, nullptr,
         CM, CDH, CM, CM, CD, CD,
         CB*CH, CH,
         (long long)CH*CM*CM, (long long)CM*CM,
         (long long)CM*CD, CDH,
         (long long)CM*CD, CDH, 1.f);

    gemm(G_PLAIN, zc, sa_Wo, Zb, nullptr, nullptr, CB*CM, CD, CD, CD, CD, CD, 1,1,0,0,0,0,0,0, 1.f);

    // ---- router ----
    gemm(G_PLAIN, h, rt_Wq, hq, nullptr, nullptr, NTOK, CD, CD, CD, CD, CD, 1,1,0,0,0,0,0,0, 1.f);
    gemm(G_TRANS, hq, Phi, lgts, nullptr, nullptr,
         CS, CM, CD, CD, CD, CM,
         CB, 1,
         (long long)CS*CD, 0, (long long)CM*CD, 0,
         (long long)CS*CM, 0, scaleD);

    router_k<<<NTOK, 256>>>(lgts, h, Zb, routed);

    // ---- output proj ----
    gemm(G_BIAS, routed, Wout, (float*)d_out, b_out, nullptr,
         NTOK, CIN, CD, CD, CIN, CIN, 1, 1, 0,0,0,0,0,0, 1.f);
}

// round 4
// speedup vs baseline: 1.5838x; 1.2602x over previous
#include <cuda_runtime.h>
#include <math.h>
#include <stdint.h>

// ---------------- problem constants ----------------
#define CB   8
#define CS   1024
#define CIN  256
#define CD   512
#define CH   8
#define CL   4
#define CM   256
#define CDFF 2048
#define CDH  64
#define NTOK (CB*CS)

// ---------------- scratch layout (floats) ----------------
constexpr long long O_H    = 0,                 S_H    = (long long)NTOK*CD;
constexpr long long O_QKV  = O_H + S_H,         S_QKV  = (long long)NTOK*3*CD;
constexpr long long O_SC   = O_QKV + S_QKV,     S_SC   = (long long)CB*CH*CS*CS;
constexpr long long O_AO   = O_SC + S_SC,       S_AO   = (long long)NTOK*CD;
constexpr long long O_FF   = O_AO + S_AO,       S_FF   = (long long)NTOK*CDFF;
constexpr long long S_BNK  = (long long)CB*CM*CD;
constexpr long long O_BQ   = O_FF + S_FF;
constexpr long long O_BK   = O_BQ + S_BNK;
constexpr long long O_BV   = O_BK + S_BNK;
constexpr long long O_ZC   = O_BV + S_BNK;
constexpr long long O_Z    = O_ZC + S_BNK;
constexpr long long O_PD   = O_Z + S_BNK,       S_PD   = (long long)CB*CM*CM;
constexpr long long O_P2   = O_PD + S_PD;
constexpr long long O_KB   = O_P2 + CB*CM;
constexpr long long O_HQ   = O_KB + CB*CM,      S_HQ   = (long long)NTOK*CD;
constexpr long long O_LG   = O_HQ + S_HQ,       S_LG   = (long long)NTOK*CM;
constexpr long long O_RT   = O_LG + S_LG,       S_RT   = (long long)NTOK*CD;
constexpr long long TOTAL_SCRATCH = O_RT + S_RT;

__device__ float g_scratch[TOTAL_SCRATCH];

// ---------------- tf32 helpers ----------------
__device__ __forceinline__ void split_tf32(float x, uint32_t &hi, uint32_t &lo)
{
    uint32_t h;
    asm("cvt.rna.tf32.f32 %0, %1;" : "=r"(h) : "f"(x));
    float hf = __uint_as_float(h);
    uint32_t l;
    asm("cvt.rna.tf32.f32 %0, %1;" : "=r"(l) : "f"(x - hf));
    hi = h; lo = l;
}

__device__ __forceinline__ void mma_tf32(float* c, const uint32_t* a, const uint32_t* b)
{
    asm volatile(
        "mma.sync.aligned.m16n8k8.row.col.f32.tf32.tf32.f32 "
        "{%0,%1,%2,%3}, {%4,%5,%6,%7}, {%8,%9}, {%0,%1,%2,%3};\n"
        : "+f"(c[0]), "+f"(c[1]), "+f"(c[2]), "+f"(c[3])
        : "r"(a[0]), "r"(a[1]), "r"(a[2]), "r"(a[3]),
          "r"(b[0]), "r"(b[1]));
}

// ---------------- 3xTF32 tensor-core GEMM, 2-stage double buffered ----------------
// C[m,n] = alpha*sum_k A[m,k]*(TRB ? B[n,k] : B[k,n]) (+bias)(+Res)(relu)
// BM=128, BN in {128,64}, BK=16. 256 threads / 8 warps.
// Requires: Mr%128==0, Nc%BN==0, Kd%16==0 (all call sites comply). No guards.
template<int BN, bool TRB, bool BIAS, bool RELU, bool RES>
__global__ __launch_bounds__(256)
void gemm_tc(const float* __restrict__ A, const float* __restrict__ B,
             float* __restrict__ C, const float* __restrict__ bias,
             const float* __restrict__ Res,
             int Kd, int lda, int ldb, int ldc, int Hb,
             long long sAb, long long sAh, long long sBb, long long sBh,
             long long sCb, long long sCh, float alpha)
{
    constexpr int SMA = 136;           // 136 % 32 == 8 -> conflict-free frag loads
    constexpr int SMB = BN + 8;        // 136 or 72, both % 32 == 8
    constexpr int SA  = 16 * SMA;
    constexpr int SB  = 16 * SMB;
    constexpr int WC  = (BN == 128) ? 4 : 2;   // warp cols
    constexpr int NI  = (BN == 128) ? 4 : 2;   // 16-row tiles per warp

    extern __shared__ float sm[];
    float* Ah = sm;
    float* Al = Ah + 2 * SA;
    float* Bh = Al + 2 * SA;
    float* Bl = Bh + 2 * SB;

    int z  = blockIdx.z;
    int zb = z / Hb, zh = z - zb * Hb;
    A += (long long)zb * sAb + (long long)zh * sAh;
    B += (long long)zb * sBb + (long long)zh * sBh;
    C += (long long)zb * sCb + (long long)zh * sCh;
    const float* Rp = RES ? (Res + (long long)zb * sCb + (long long)zh * sCh) : nullptr;

    const int m0   = blockIdx.y * 128;
    const int n0   = blockIdx.x * BN;
    const int tid  = threadIdx.x;
    const int lane = tid & 31, warp = tid >> 5;
    const int wm   = (warp / WC) * (NI * 16);
    const int wn   = (warp % WC) * 32;
    const int g    = lane >> 2, kq = lane & 3;

    // staging maps
    const int amm = tid >> 1, akt = (tid & 1) << 3;   // A rows / TRB-B rows, 8 floats along k
    const int bkk = tid >> 4, bnn = (tid & 15) << 3;  // BN128 non-TRB: 8 floats along n
    const int ckk = tid >> 4, cnn = (tid & 15) << 2;  // BN64  non-TRB: 4 floats along n

    float acc[NI][4][4];
    #pragma unroll
    for (int i = 0; i < NI; i++)
        #pragma unroll
        for (int j = 0; j < 4; j++)
            #pragma unroll
            for (int r = 0; r < 4; r++) acc[i][j][r] = 0.f;

    float va[8], vb[8];

    auto loadA = [&](int kt) {
        const float* p = A + (long long)(m0 + amm) * lda + kt + akt;
        float4 u0 = *(const float4*)p, u1 = *(const float4*)(p + 4);
        va[0]=u0.x; va[1]=u0.y; va[2]=u0.z; va[3]=u0.w;
        va[4]=u1.x; va[5]=u1.y; va[6]=u1.z; va[7]=u1.w;
    };
    auto storeA = [&](int st) {
        float* ph = Ah + st * SA;
        float* pl = Al + st * SA;
        #pragma unroll
        for (int u = 0; u < 8; u++) {
            uint32_t h, l; split_tf32(va[u], h, l);
            ph[(akt + u) * SMA + amm] = __uint_as_float(h);
            pl[(akt + u) * SMA + amm] = __uint_as_float(l);
        }
    };
    auto loadB = [&](int kt) {
        if constexpr (TRB) {
            const float* p = B + (long long)(n0 + amm) * ldb + kt + akt;
            float4 u0 = *(const float4*)p, u1 = *(const float4*)(p + 4);
            vb[0]=u0.x; vb[1]=u0.y; vb[2]=u0.z; vb[3]=u0.w;
            vb[4]=u1.x; vb[5]=u1.y; vb[6]=u1.z; vb[7]=u1.w;
        } else if constexpr (BN == 128) {
            const float* p = B + (long long)(kt + bkk) * ldb + n0 + bnn;
            float4 u0 = *(const float4*)p, u1 = *(const float4*)(p + 4);
            vb[0]=u0.x; vb[1]=u0.y; vb[2]=u0.z; vb[3]=u0.w;
            vb[4]=u1.x; vb[5]=u1.y; vb[6]=u1.z; vb[7]=u1.w;
        } else {
            const float* p = B + (long long)(kt + ckk) * ldb + n0 + cnn;
            float4 u0 = *(const float4*)p;
            vb[0]=u0.x; vb[1]=u0.y; vb[2]=u0.z; vb[3]=u0.w;
        }
    };
    auto storeB = [&](int st) {
        if constexpr (TRB) {
            float* ph = Bh + st * SB;
            float* pl = Bl + st * SB;
            #pragma unroll
            for (int u = 0; u < 8; u++) {
                uint32_t h, l; split_tf32(vb[u], h, l);
                ph[(akt + u) * SMB + amm] = __uint_as_float(h);
                pl[(akt + u) * SMB + amm] = __uint_as_float(l);
            }
        } else if constexpr (BN == 128) {
            float hv[8], lv[8];
            #pragma unroll
            for (int u = 0; u < 8; u++) {
                uint32_t h, l; split_tf32(vb[u], h, l);
                hv[u] = __uint_as_float(h); lv[u] = __uint_as_float(l);
            }
            float* ph = Bh + st * SB + bkk * SMB + bnn;
            float* pl = Bl + st * SB + bkk * SMB + bnn;
            *(float4*)ph       = make_float4(hv[0],hv[1],hv[2],hv[3]);
            *(float4*)(ph + 4) = make_float4(hv[4],hv[5],hv[6],hv[7]);
            *(float4*)pl       = make_float4(lv[0],lv[1],lv[2],lv[3]);
            *(float4*)(pl + 4) = make_float4(lv[4],lv[5],lv[6],lv[7]);
        } else {
            float hv[4], lv[4];
            #pragma unroll
            for (int u = 0; u < 4; u++) {
                uint32_t h, l; split_tf32(vb[u], h, l);
                hv[u] = __uint_as_float(h); lv[u] = __uint_as_float(l);
            }
            float* ph = Bh + st * SB + ckk * SMB + cnn;
            float* pl = Bl + st * SB + ckk * SMB + cnn;
            *(float4*)ph = make_float4(hv[0],hv[1],hv[2],hv[3]);
            *(float4*)pl = make_float4(lv[0],lv[1],lv[2],lv[3]);
        }
    };
    auto compute = [&](int st) {
        const float* pah = Ah + st * SA;
        const float* pal = Al + st * SA;
        const float* pbh = Bh + st * SB;
        const float* pbl = Bl + st * SB;
        #pragma unroll
        for (int ks = 0; ks < 16; ks += 8) {
            uint32_t ah[NI][4], al[NI][4], bh[4][2], bl[4][2];
            #pragma unroll
            for (int i = 0; i < NI; i++) {
                int base = (ks + kq) * SMA + wm + 16 * i + g;
                ah[i][0] = __float_as_uint(pah[base]);
                ah[i][1] = __float_as_uint(pah[base + 8]);
                ah[i][2] = __float_as_uint(pah[base + 4 * SMA]);
                ah[i][3] = __float_as_uint(pah[base + 4 * SMA + 8]);
                al[i][0] = __float_as_uint(pal[base]);
                al[i][1] = __float_as_uint(pal[base + 8]);
                al[i][2] = __float_as_uint(pal[base + 4 * SMA]);
                al[i][3] = __float_as_uint(pal[base + 4 * SMA + 8]);
            }
            #pragma unroll
            for (int j = 0; j < 4; j++) {
                int cb = (ks + kq) * SMB + wn + 8 * j + g;
                bh[j][0] = __float_as_uint(pbh[cb]);
                bh[j][1] = __float_as_uint(pbh[cb + 4 * SMB]);
                bl[j][0] = __float_as_uint(pbl[cb]);
                bl[j][1] = __float_as_uint(pbl[cb + 4 * SMB]);
            }
            #pragma unroll
            for (int i = 0; i < NI; i++)
                #pragma unroll
                for (int j = 0; j < 4; j++) {
                    mma_tf32(acc[i][j], ah[i], bl[j]);
                    mma_tf32(acc[i][j], al[i], bh[j]);
                    mma_tf32(acc[i][j], ah[i], bh[j]);
                }
        }
    };

    // ---- 2-stage pipeline, one sync per k-tile ----
    loadA(0); loadB(0);
    storeA(0); storeB(0);
    const int nIt = Kd >> 4;
    for (int it = 0; it < nIt; it++) {
        __syncthreads();
        bool more = (it + 1 < nIt);
        if (more) { loadA((it + 1) << 4); loadB((it + 1) << 4); }
        compute(it & 1);
        if (more) { storeA((it + 1) & 1); storeB((it + 1) & 1); }
    }

    // ---- epilogue ----
    #pragma unroll
    for (int i = 0; i < NI; i++) {
        int r0 = m0 + wm + 16 * i + g;
        int r1 = r0 + 8;
        #pragma unroll
        for (int j = 0; j < 4; j++) {
            int col = n0 + wn + 8 * j + 2 * kq;
            float b0 = 0.f, b1 = 0.f;
            if (BIAS) { b0 = bias[col]; b1 = bias[col + 1]; }
            {
                float v0 = acc[i][j][0] * alpha + b0;
                float v1 = acc[i][j][1] * alpha + b1;
                if (RES) {
                    const float* rp = Rp + (long long)r0 * ldc + col;
                    v0 += rp[0]; v1 += rp[1];
                }
                if (RELU) { v0 = fmaxf(v0, 0.f); v1 = fmaxf(v1, 0.f); }
                *(float2*)&C[(long long)r0 * ldc + col] = make_float2(v0, v1);
            }
            {
                float v0 = acc[i][j][2] * alpha + b0;
                float v1 = acc[i][j][3] * alpha + b1;
                if (RES) {
                    const float* rp = Rp + (long long)r1 * ldc + col;
                    v0 += rp[0]; v1 += rp[1];
                }
                if (RELU) { v0 = fmaxf(v0, 0.f); v1 = fmaxf(v1, 0.f); }
                *(float2*)&C[(long long)r1 * ldc + col] = make_float2(v0, v1);
            }
        }
    }
}

// ---------------- elementwise / reduction kernels ----------------

__global__ void add_pe_k(float* __restrict__ h, const float* __restrict__ temb)
{
    long long idx = (long long)blockIdx.x * 256 + threadIdx.x;
    if (idx >= (long long)NTOK * CD) return;
    int d = (int)(idx & (CD-1));
    long long bs = idx >> 9;
    int s  = (int)(bs & (CS-1));
    int bb = (int)(bs >> 10);
    int i2 = d & ~1;
    float dv  = expf((float)i2 * (-9.210340371976184f / (float)CD));
    float ang = (float)s * dv;
    float pe  = (d & 1) ? cosf(ang) : sinf(ang);
    h[idx] += pe + temb[(long long)bb*CD + d];
}

__global__ __launch_bounds__(256)
void softmax1024_k(float* __restrict__ X)
{
    long long row = blockIdx.x;
    float4* x = (float4*)(X + row * 1024);
    int tid = threadIdx.x;
    float4 v = x[tid];
    __shared__ float red[8];

    float m = fmaxf(fmaxf(v.x, v.y), fmaxf(v.z, v.w));
    #pragma unroll
    for (int off = 16; off > 0; off >>= 1)
        m = fmaxf(m, __shfl_xor_sync(0xffffffffu, m, off));
    if ((tid & 31) == 0) red[tid >> 5] = m;
    __syncthreads();
    m = red[0];
    #pragma unroll
    for (int w = 1; w < 8; w++) m = fmaxf(m, red[w]);

    v.x = __expf(v.x - m); v.y = __expf(v.y - m);
    v.z = __expf(v.z - m); v.w = __expf(v.w - m);
    float s = v.x + v.y + v.z + v.w;
    #pragma unroll
    for (int off = 16; off > 0; off >>= 1)
        s += __shfl_xor_sync(0xffffffffu, s, off);
    __syncthreads();
    if ((tid & 31) == 0) red[tid >> 5] = s;
    __syncthreads();
    s = red[0];
    #pragma unroll
    for (int w = 1; w < 8; w++) s += red[w];

    float inv = 1.f / s;
    v.x *= inv; v.y *= inv; v.z *= inv; v.w *= inv;
    x[tid] = v;
}

__global__ void softmax_rows_k(float* __restrict__ X, int ncols)
{
    long long row = blockIdx.x;
    float* x = X + row * (long long)ncols;
    __shared__ float red[256];
    int tid = threadIdx.x;
    float m = -3.0e38f;
    for (int c = tid; c < ncols; c += 256) m = fmaxf(m, x[c]);
    red[tid] = m; __syncthreads();
    for (int off = 128; off > 0; off >>= 1) {
        if (tid < off) red[tid] = fmaxf(red[tid], red[tid+off]);
        __syncthreads();
    }
    float mx = red[0];
    __syncthreads();
    float s = 0.f;
    for (int c = tid; c < ncols; c += 256) { float e = __expf(x[c]-mx); x[c] = e; s += e; }
    red[tid] = s; __syncthreads();
    for (int off = 128; off > 0; off >>= 1) {
        if (tid < off) red[tid] += red[tid+off];
        __syncthreads();
    }
    float inv = 1.f / red[0];
    for (int c = tid; c < ncols; c += 256) x[c] *= inv;
}

__global__ void layernorm512_k(float* __restrict__ X, const float* __restrict__ g,
                               const float* __restrict__ b)
{
    long long row = blockIdx.x;
    float* x = X + row * (long long)CD;
    __shared__ float red[256];
    int tid = threadIdx.x;
    float v0 = x[tid], v1 = x[tid+256];
    red[tid] = v0 + v1; __syncthreads();
    for (int off = 128; off > 0; off >>= 1) {
        if (tid < off) red[tid] += red[tid+off];
        __syncthreads();
    }
    float mu = red[0] * (1.f/512.f);
    __syncthreads();
    float d0 = v0 - mu, d1 = v1 - mu;
    red[tid] = d0*d0 + d1*d1; __syncthreads();
    for (int off = 128; off > 0; off >>= 1) {
        if (tid < off) red[tid] += red[tid+off];
        __syncthreads();
    }
    float var = red[0] * (1.f/512.f);
    float rs = 1.f / sqrtf(var + 1e-5f);
    x[tid]     = d0*rs*g[tid]     + b[tid];
    x[tid+256] = d1*rs*g[tid+256] + b[tid+256];
}

__global__ void bank_prep_k(const float* __restrict__ Phi, const float* __restrict__ Sig,
                            const float* __restrict__ Size,
                            float* __restrict__ p2, float* __restrict__ kb)
{
    int i = blockIdx.x * 256 + threadIdx.x;
    if (i >= CB*CM) return;
    const float* ph = Phi + (long long)i*CD;
    const float* sg = Sig + (long long)i*CD;
    float s = 0.f, s2 = 0.f;
    for (int d = 0; d < CD; d++) { s += ph[d]*ph[d]; s2 += sg[d]*sg[d]; }
    p2[i] = s;
    kb[i] = 0.3f * logf(Size[i] + 1e-6f) - 0.5f * (s2 * (1.f/(float)CD));
}

__global__ void bank_scores_k(float* __restrict__ Sdot, const float* __restrict__ phidot,
                              const float* __restrict__ p2, const float* __restrict__ kb)
{
    long long idx = (long long)blockIdx.x * 256 + threadIdx.x;
    if (idx >= (long long)CB*CH*CM*CM) return;
    int n = (int)(idx & (CM-1));
    long long t = idx >> 8;
    int m = (int)(t & (CM-1));
    long long t2 = t >> 8;
    int bb = (int)(t2 >> 3);
    float d2 = p2[bb*CM + m] + p2[bb*CM + n]
             - 2.f * phidot[((long long)bb*CM + m)*CM + n];
    Sdot[idx] = Sdot[idx] - d2 * (1.f/(float)CD) + kb[bb*CM + n];
}

__global__ void router_k(const float* __restrict__ logits, const float* __restrict__ h,
                         const float* __restrict__ Z, float* __restrict__ out)
{
    int row = blockIdx.x;
    int bb  = row >> 10;
    const float* lg = logits + (long long)row * CM;
    __shared__ float sv[256];
    __shared__ float rv[256];
    __shared__ int   ri[256];
    __shared__ float topv[4];
    __shared__ int   topi[4];
    __shared__ float w[4];
    int tid = threadIdx.x;
    sv[tid] = lg[tid];
    __syncthreads();
    for (int kk = 0; kk < 4; kk++) {
        rv[tid] = sv[tid]; ri[tid] = tid;
        __syncthreads();
        for (int off = 128; off > 0; off >>= 1) {
            if (tid < off) {
                float v2 = rv[tid+off]; int i2 = ri[tid+off];
                if (v2 > rv[tid] || (v2 == rv[tid] && i2 < ri[tid])) { rv[tid] = v2; ri[tid] = i2; }
            }
            __syncthreads();
        }
        if (tid == 0) {
            topv[kk] = rv[0]; topi[kk] = ri[0];
            sv[ri[0]] = -3.0e38f;
        }
        __syncthreads();
    }
    if (tid == 0) {
        float mx = topv[0];
        float e0 = __expf(topv[0]-mx), e1 = __expf(topv[1]-mx),
              e2 = __expf(topv[2]-mx), e3 = __expf(topv[3]-mx);
        float inv = 1.f / (e0+e1+e2+e3);
        w[0]=e0*inv; w[1]=e1*inv; w[2]=e2*inv; w[3]=e3*inv;
    }
    __syncthreads();
    const float* hr = h + (long long)row*CD;
    float w0=w[0], w1=w[1], w2=w[2], w3=w[3];
    const float* z0 = Z + ((long long)bb*CM + topi[0])*CD;
    const float* z1 = Z + ((long long)bb*CM + topi[1])*CD;
    const float* z2 = Z + ((long long)bb*CM + topi[2])*CD;
    const float* z3 = Z + ((long long)bb*CM + topi[3])*CD;
    for (int d = tid; d < CD; d += 256)
        out[(long long)row*CD + d] = hr[d] + w0*z0[d] + w1*z1[d] + w2*z2[d] + w3*z3[d];
}

// ---------------- host side ----------------

enum GMode { G_PLAIN, G_BIAS, G_BIAS_RES, G_BIAS_RELU, G_TRANS };

constexpr int SHM128 = (8 * 16 * 136) * 4;                    // 69632 B
constexpr int SHM64  = (4 * 16 * 136 + 4 * 16 * 72) * 4;      // 53248 B

static inline void gemm(GMode mode, int bn, const float* A, const float* Bm, float* C,
                        const float* bias, const float* Res,
                        int Mr, int Nc, int Kd, int lda, int ldb, int ldc,
                        int batches, int Hb,
                        long long sAb, long long sAh,
                        long long sBb, long long sBh,
                        long long sCb, long long sCh, float alpha)
{
    dim3 grid(Nc / bn, Mr / 128, batches);
    if (bn == 64) {
        cudaFuncSetAttribute(gemm_tc<64,false,false,false,false>,
                             cudaFuncAttributeMaxDynamicSharedMemorySize, SHM64);
        gemm_tc<64,false,false,false,false><<<grid,256,SHM64>>>(
            A,Bm,C,bias,Res,Kd,lda,ldb,ldc,Hb,sAb,sAh,sBb,sBh,sCb,sCh,alpha);
        return;
    }
    switch (mode) {
    case G_PLAIN:
        cudaFuncSetAttribute(gemm_tc<128,false,false,false,false>,
                             cudaFuncAttributeMaxDynamicSharedMemorySize, SHM128);
        gemm_tc<128,false,false,false,false><<<grid,256,SHM128>>>(
            A,Bm,C,bias,Res,Kd,lda,ldb,ldc,Hb,sAb,sAh,sBb,sBh,sCb,sCh,alpha); break;
    case G_BIAS:
        cudaFuncSetAttribute(gemm_tc<128,false,true,false,false>,
                             cudaFuncAttributeMaxDynamicSharedMemorySize, SHM128);
        gemm_tc<128,false,true,false,false><<<grid,256,SHM128>>>(
            A,Bm,C,bias,Res,Kd,lda,ldb,ldc,Hb,sAb,sAh,sBb,sBh,sCb,sCh,alpha); break;
    case G_BIAS_RES:
        cudaFuncSetAttribute(gemm_tc<128,false,true,false,true>,
                             cudaFuncAttributeMaxDynamicSharedMemorySize, SHM128);
        gemm_tc<128,false,true,false,true><<<grid,256,SHM128>>>(
            A,Bm,C,bias,Res,Kd,lda,ldb,ldc,Hb,sAb,sAh,sBb,sBh,sCb,sCh,alpha); break;
    case G_BIAS_RELU:
        cudaFuncSetAttribute(gemm_tc<128,false,true,true,false>,
                             cudaFuncAttributeMaxDynamicSharedMemorySize, SHM128);
        gemm_tc<128,false,true,true,false><<<grid,256,SHM128>>>(
            A,Bm,C,bias,Res,Kd,lda,ldb,ldc,Hb,sAb,sAh,sBb,sBh,sCb,sCh,alpha); break;
    case G_TRANS:
        cudaFuncSetAttribute(gemm_tc<128,true,false,false,false>,
                             cudaFuncAttributeMaxDynamicSharedMemorySize, SHM128);
        gemm_tc<128,true,false,false,false><<<grid,256,SHM128>>>(
            A,Bm,C,bias,Res,Kd,lda,ldb,ldc,Hb,sAb,sAh,sBb,sBh,sCb,sCh,alpha); break;
    }
}

extern "C" void kernel_launch(void* const* d_in, const int* in_sizes, int n_in,
                              void* d_out, int out_size)
{
    const float* x_t      = (const float*)d_in[0];
    const float* t_embed  = (const float*)d_in[1];
    const float* Phi      = (const float*)d_in[2];
    const float* Sig      = (const float*)d_in[3];
    const float* Size     = (const float*)d_in[4];
    /* d_in[5] = mask: all-True, ignored */
    const float* Win      = (const float*)d_in[6];
    const float* b_in     = (const float*)d_in[7];
    const float* Wout     = (const float*)d_in[8];
    const float* b_out    = (const float*)d_in[9];
    const float* enc_Wqkv = (const float*)d_in[10];
    const float* enc_bqkv = (const float*)d_in[11];
    const float* enc_Wo   = (const float*)d_in[12];
    const float* enc_bo   = (const float*)d_in[13];
    const float* ln1_g    = (const float*)d_in[14];
    const float* ln1_b    = (const float*)d_in[15];
    const float* ln2_g    = (const float*)d_in[16];
    const float* ln2_b    = (const float*)d_in[17];
    const float* ff_W1    = (const float*)d_in[18];
    const float* ff_b1    = (const float*)d_in[19];
    const float* ff_W2    = (const float*)d_in[20];
    const float* ff_b2    = (const float*)d_in[21];
    const float* sa_Wq    = (const float*)d_in[22];
    const float* sa_Wk    = (const float*)d_in[23];
    const float* sa_Wv    = (const float*)d_in[24];
    const float* sa_Wo    = (const float*)d_in[25];
    const float* rt_Wq    = (const float*)d_in[26];

    float* sc = nullptr;
    cudaGetSymbolAddress((void**)&sc, g_scratch);
    float* h      = sc + O_H;
    float* qkv    = sc + O_QKV;
    float* scores = sc + O_SC;
    float* attno  = sc + O_AO;
    float* ff     = sc + O_FF;
    float* bq     = sc + O_BQ;
    float* bk     = sc + O_BK;
    float* bv     = sc + O_BV;
    float* zc     = sc + O_ZC;
    float* Zb     = sc + O_Z;
    float* phidot = sc + O_PD;
    float* p2     = sc + O_P2;
    float* kb     = sc + O_KB;
    float* hq     = sc + O_HQ;
    float* lgts   = sc + O_LG;
    float* routed = sc + O_RT;

    const float scaleDH = 0.125f;
    const float scaleD  = 0.04419417382415922f;

    // ---- input proj + PE + t_embed ----
    gemm(G_BIAS, 128, x_t, Win, h, b_in, nullptr,
         NTOK, CD, CIN, CIN, CD, CD, 1, 1, 0,0,0,0,0,0, 1.f);
    add_pe_k<<<(NTOK*(long long)CD + 255)/256, 256>>>(h, t_embed);

    // ---- encoder layers ----
    for (int l = 0; l < CL; l++) {
        const float* Wqkv = enc_Wqkv + (long long)l*CD*3*CD;
        const float* bqkv = enc_bqkv + (long long)l*3*CD;
        const float* Wo   = enc_Wo   + (long long)l*CD*CD;
        const float* bo   = enc_bo   + (long long)l*CD;

        gemm(G_BIAS, 128, h, Wqkv, qkv, bqkv, nullptr,
             NTOK, 3*CD, CD, CD, 3*CD, 3*CD, 1, 1, 0,0,0,0,0,0, 1.f);

        gemm(G_TRANS, 128, qkv, qkv + CD, scores, nullptr, nullptr,
             CS, CS, CDH, 3*CD, 3*CD, CS,
             CB*CH, CH,
             (long long)CS*3*CD, CDH,
             (long long)CS*3*CD, CDH,
             (long long)CH*CS*CS, (long long)CS*CS, scaleDH);

        softmax1024_k<<<CB*CH*CS, 256>>>(scores);

        gemm(G_PLAIN, 64, scores, qkv + 2*CD, attno, nullptr, nullptr,
             CS, CDH, CS, CS, 3*CD, CD,
             CB*CH, CH,
             (long long)CH*CS*CS, (long long)CS*CS,
             (long long)CS*3*CD, CDH,
             (long long)CS*CD, CDH, 1.f);

        gemm(G_BIAS_RES, 128, attno, Wo, h, bo, h,
             NTOK, CD, CD, CD, CD, CD, 1, 1, 0,0,0,0,0,0, 1.f);
        layernorm512_k<<<NTOK, 256>>>(h, ln1_g + (long long)l*CD, ln1_b + (long long)l*CD);

        gemm(G_BIAS_RELU, 128, h, ff_W1 + (long long)l*CD*CDFF, ff,
             ff_b1 + (long long)l*CDFF, nullptr,
             NTOK, CDFF, CD, CD, CDFF, CDFF, 1, 1, 0,0,0,0,0,0, 1.f);
        gemm(G_BIAS_RES, 128, ff, ff_W2 + (long long)l*CDFF*CD, h,
             ff_b2 + (long long)l*CD, h,
             NTOK, CD, CDFF, CDFF, CD, CD, 1, 1, 0,0,0,0,0,0, 1.f);
        layernorm512_k<<<NTOK, 256>>>(h, ln2_g + (long long)l*CD, ln2_b + (long long)l*CD);
    }

    // ---- SetBankAttention ----
    gemm(G_PLAIN, 128, Phi, sa_Wq, bq, nullptr, nullptr, CB*CM, CD, CD, CD, CD, CD, 1,1,0,0,0,0,0,0, 1.f);
    gemm(G_PLAIN, 128, Phi, sa_Wk, bk, nullptr, nullptr, CB*CM, CD, CD, CD, CD, CD, 1,1,0,0,0,0,0,0, 1.f);
    gemm(G_PLAIN, 128, Phi, sa_Wv, bv, nullptr, nullptr, CB*CM, CD, CD, CD, CD, CD, 1,1,0,0,0,0,0,0, 1.f);

    gemm(G_TRANS, 128, Phi, Phi, phidot, nullptr, nullptr,
         CM, CM, CD, CD, CD, CM,
         CB, 1,
         (long long)CM*CD, 0, (long long)CM*CD, 0,
         (long long)CM*CM, 0, 1.f);

    gemm(G_TRANS, 128, bq, bk, scores, nullptr, nullptr,
         CM, CM, CDH, CD, CD, CM,
         CB*CH, CH,
         (long long)CM*CD, CDH,
         (long long)CM*CD, CDH,
         (long long)CH*CM*CM, (long long)CM*CM, scaleDH);

    bank_prep_k<<<(CB*CM + 255)/256, 256>>>(Phi, Sig, Size, p2, kb);
    bank_scores_k<<<((long long)CB*CH*CM*CM + 255)/256, 256>>>(scores, phidot, p2, kb);
    softmax_rows_k<<<CB*CH*CM, 256>>>(scores, CM);

    gemm(G_PLAIN, 64, scores, bv, zc, nullptr, nullptr,
         CM, CDH, CM, CM, CD, CD,
         CB*CH, CH,
         (long long)CH*CM*CM, (long long)CM*CM,
         (long long)CM*CD, CDH,
         (long long)CM*CD, CDH, 1.f);

    gemm(G_PLAIN, 128, zc, sa_Wo, Zb, nullptr, nullptr, CB*CM, CD, CD, CD, CD, CD, 1,1,0,0,0,0,0,0, 1.f);

    // ---- router ----
    gemm(G_PLAIN, 128, h, rt_Wq, hq, nullptr, nullptr, NTOK, CD, CD, CD, CD, CD, 1,1,0,0,0,0,0,0, 1.f);
    gemm(G_TRANS, 128, hq, Phi, lgts, nullptr, nullptr,
         CS, CM, CD, CD, CD, CM,
         CB, 1,
         (long long)CS*CD, 0, (long long)CM*CD, 0,
         (long long)CS*CM, 0, scaleD);

    router_k<<<NTOK, 256>>>(lgts, h, Zb, routed);

    // ---- output proj ----
    gemm(G_BIAS, 128, routed, Wout, (float*)d_out, b_out, nullptr,
         NTOK, CIN, CD, CD, CIN, CIN, 1, 1, 0,0,0,0,0,0, 1.f);
}

// round 6
// speedup vs baseline: 1.8311x; 1.1561x over previous
#include <cuda_runtime.h>
#include <math.h>
#include <stdint.h>

// ---------------- problem constants ----------------
#define CB   8
#define CS   1024
#define CIN  256
#define CD   512
#define CH   8
#define CL   4
#define CM   256
#define CDFF 2048
#define CDH  64
#define NTOK (CB*CS)

// ---------------- scratch layout (floats) ----------------
constexpr long long O_H    = 0,                 S_H    = (long long)NTOK*CD;
constexpr long long O_QKV  = O_H + S_H,         S_QKV  = (long long)NTOK*3*CD;
constexpr long long O_SC   = O_QKV + S_QKV,     S_SC   = (long long)CB*CH*CS*CS;
constexpr long long O_AO   = O_SC + S_SC,       S_AO   = (long long)NTOK*CD;
constexpr long long O_FF   = O_AO + S_AO,       S_FF   = (long long)NTOK*CDFF;
constexpr long long S_BNK  = (long long)CB*CM*CD;
constexpr long long O_BQ   = O_FF + S_FF;
constexpr long long O_BK   = O_BQ + S_BNK;
constexpr long long O_BV   = O_BK + S_BNK;
constexpr long long O_ZC   = O_BV + S_BNK;
constexpr long long O_Z    = O_ZC + S_BNK;
constexpr long long O_PD   = O_Z + S_BNK,       S_PD   = (long long)CB*CM*CM;
constexpr long long O_P2   = O_PD + S_PD;
constexpr long long O_KB   = O_P2 + CB*CM;
constexpr long long O_HQ   = O_KB + CB*CM,      S_HQ   = (long long)NTOK*CD;
constexpr long long O_LG   = O_HQ + S_HQ,       S_LG   = (long long)NTOK*CM;
constexpr long long O_RT   = O_LG + S_LG,       S_RT   = (long long)NTOK*CD;
constexpr long long TOTAL_SCRATCH = O_RT + S_RT;

__device__ float g_scratch[TOTAL_SCRATCH];

// ---------------- helpers ----------------
__device__ __forceinline__ void split_tf32(float x, uint32_t &hi, uint32_t &lo)
{
    uint32_t h;
    asm("cvt.rna.tf32.f32 %0, %1;" : "=r"(h) : "f"(x));
    float hf = __uint_as_float(h);
    uint32_t l;
    asm("cvt.rna.tf32.f32 %0, %1;" : "=r"(l) : "f"(x - hf));
    hi = h; lo = l;
}

__device__ __forceinline__ void mma_tf32(float* c, const uint32_t* a, const uint32_t* b)
{
    asm volatile(
        "mma.sync.aligned.m16n8k8.row.col.f32.tf32.tf32.f32 "
        "{%0,%1,%2,%3}, {%4,%5,%6,%7}, {%8,%9}, {%0,%1,%2,%3};\n"
        : "+f"(c[0]), "+f"(c[1]), "+f"(c[2]), "+f"(c[3])
        : "r"(a[0]), "r"(a[1]), "r"(a[2]), "r"(a[3]),
          "r"(b[0]), "r"(b[1]));
}

__device__ __forceinline__ void cpa16(float* dst_smem, const float* src)
{
    uint32_t d = (uint32_t)__cvta_generic_to_shared(dst_smem);
    asm volatile("cp.async.cg.shared.global [%0], [%1], 16;\n" :: "r"(d), "l"(src));
}
__device__ __forceinline__ void cpa_commit()
{
    asm volatile("cp.async.commit_group;\n");
}
__device__ __forceinline__ void cpa_wait1()
{
    asm volatile("cp.async.wait_group 1;\n");
}

// ---------------- 3xTF32 GEMM, cp.async 3-stage, 2 CTAs/SM ----------------
// C[m,n] = alpha*sum_k A[m,k]*(TRB ? B[n,k] : B[k,n]) (+bias)(+Res)(relu)
// BM=128, BN in {128,64}, BK=16, 3 smem stages of raw fp32, split at frag load.
// Requires: Mr%128==0, Nc%BN==0, Kd%16==0. No bounds guards.
template<int BN, bool TRB, bool BIAS, bool RELU, bool RES>
__global__ __launch_bounds__(256, 2)
void gemm_ca(const float* __restrict__ A, const float* __restrict__ B,
             float* __restrict__ C, const float* __restrict__ bias,
             const float* __restrict__ Res,
             int Kd, int lda, int ldb, int ldc, int Hb,
             long long sAb, long long sAh, long long sBb, long long sBh,
             long long sCb, long long sCh, float alpha)
{
    constexpr int SMA  = 20;                       // [m][k] row stride (16+4 pad)
    constexpr int SAsz = 128 * SMA;                // floats per A stage
    constexpr int SMB  = TRB ? 20 : (BN + 8);
    constexpr int SBsz = TRB ? (BN * SMB) : (16 * SMB);
    constexpr int WC   = (BN == 128) ? 4 : 2;
    constexpr int NI   = (BN == 128) ? 4 : 2;

    extern __shared__ float sm[];
    float* As = sm;                                // 3 stages
    float* Bs = sm + 3 * SAsz;

    int z  = blockIdx.z;
    int zb = z / Hb, zh = z - zb * Hb;
    A += (long long)zb * sAb + (long long)zh * sAh;
    B += (long long)zb * sBb + (long long)zh * sBh;
    C += (long long)zb * sCb + (long long)zh * sCh;
    const float* Rp = RES ? (Res + (long long)zb * sCb + (long long)zh * sCh) : nullptr;

    const int m0   = blockIdx.y * 128;
    const int n0   = blockIdx.x * BN;
    const int tid  = threadIdx.x;
    const int lane = tid & 31, warp = tid >> 5;
    const int wm   = (warp / WC) * (NI * 16);
    const int wn   = (warp % WC) * 32;
    const int g    = lane >> 2, kq = lane & 3;

    float acc[NI][4][4];
    #pragma unroll
    for (int i = 0; i < NI; i++)
        #pragma unroll
        for (int j = 0; j < 4; j++)
            #pragma unroll
            for (int r = 0; r < 4; r++) acc[i][j][r] = 0.f;

    // copy maps
    const int ar = tid >> 2, ac = (tid & 3) << 2;          // A / TRB-B: rows, 4-float chunk
    const int br = tid >> 4, bc = (tid & 15) << 2;         // non-TRB B: k-row, 4-float chunk

    auto copyAB = [&](int st, int kt) {
        float* pa = As + st * SAsz;
        cpa16(pa + ar * SMA + ac, A + (long long)(m0 + ar) * lda + kt + ac);
        cpa16(pa + (ar + 64) * SMA + ac, A + (long long)(m0 + ar + 64) * lda + kt + ac);
        float* pb = Bs + st * SBsz;
        if constexpr (TRB) {
            cpa16(pb + ar * SMA + ac, B + (long long)(n0 + ar) * ldb + kt + ac);
            cpa16(pb + (ar + 64) * SMA + ac, B + (long long)(n0 + ar + 64) * ldb + kt + ac);
        } else if constexpr (BN == 128) {
            cpa16(pb + br * SMB + bc, B + (long long)(kt + br) * ldb + n0 + bc);
            cpa16(pb + br * SMB + bc + 64, B + (long long)(kt + br) * ldb + n0 + bc + 64);
        } else {
            cpa16(pb + br * SMB + bc, B + (long long)(kt + br) * ldb + n0 + bc);
        }
    };

    auto compute = [&](int st) {
        const float* pA = As + st * SAsz;
        const float* pB = Bs + st * SBsz;
        #pragma unroll
        for (int ks = 0; ks < 16; ks += 8) {
            uint32_t ah[NI][4], al[NI][4], bh[4][2], bl[4][2];
            #pragma unroll
            for (int i = 0; i < NI; i++) {
                int r = wm + 16 * i + g;
                split_tf32(pA[r * SMA + ks + kq],           ah[i][0], al[i][0]);
                split_tf32(pA[(r + 8) * SMA + ks + kq],     ah[i][1], al[i][1]);
                split_tf32(pA[r * SMA + ks + kq + 4],       ah[i][2], al[i][2]);
                split_tf32(pA[(r + 8) * SMA + ks + kq + 4], ah[i][3], al[i][3]);
            }
            #pragma unroll
            for (int j = 0; j < 4; j++) {
                if constexpr (TRB) {
                    int n = wn + 8 * j + g;
                    split_tf32(pB[n * SMB + ks + kq],     bh[j][0], bl[j][0]);
                    split_tf32(pB[n * SMB + ks + kq + 4], bh[j][1], bl[j][1]);
                } else {
                    int n = wn + 8 * j + g;
                    split_tf32(pB[(ks + kq) * SMB + n],     bh[j][0], bl[j][0]);
                    split_tf32(pB[(ks + kq + 4) * SMB + n], bh[j][1], bl[j][1]);
                }
            }
            #pragma unroll
            for (int i = 0; i < NI; i++)
                #pragma unroll
                for (int j = 0; j < 4; j++) {
                    mma_tf32(acc[i][j], ah[i], bl[j]);
                    mma_tf32(acc[i][j], al[i], bh[j]);
                    mma_tf32(acc[i][j], ah[i], bh[j]);
                }
        }
    };

    // ---- 3-stage pipeline ----
    const int nIt = Kd >> 4;
    copyAB(0, 0); cpa_commit();
    if (nIt > 1) copyAB(1, 16);
    cpa_commit();                       // group even if empty
    for (int it = 0; it < nIt; it++) {
        cpa_wait1();
        __syncthreads();
        compute(it % 3);
        int kn = (it + 2) << 4;
        if (kn < Kd) copyAB((it + 2) % 3, kn);
        cpa_commit();                   // empty commits keep group count uniform
    }

    // ---- epilogue ----
    #pragma unroll
    for (int i = 0; i < NI; i++) {
        int r0 = m0 + wm + 16 * i + g;
        int r1 = r0 + 8;
        #pragma unroll
        for (int j = 0; j < 4; j++) {
            int col = n0 + wn + 8 * j + 2 * kq;
            float b0 = 0.f, b1 = 0.f;
            if (BIAS) { b0 = bias[col]; b1 = bias[col + 1]; }
            {
                float v0 = acc[i][j][0] * alpha + b0;
                float v1 = acc[i][j][1] * alpha + b1;
                if (RES) {
                    const float* rp = Rp + (long long)r0 * ldc + col;
                    v0 += rp[0]; v1 += rp[1];
                }
                if (RELU) { v0 = fmaxf(v0, 0.f); v1 = fmaxf(v1, 0.f); }
                *(float2*)&C[(long long)r0 * ldc + col] = make_float2(v0, v1);
            }
            {
                float v0 = acc[i][j][2] * alpha + b0;
                float v1 = acc[i][j][3] * alpha + b1;
                if (RES) {
                    const float* rp = Rp + (long long)r1 * ldc + col;
                    v0 += rp[0]; v1 += rp[1];
                }
                if (RELU) { v0 = fmaxf(v0, 0.f); v1 = fmaxf(v1, 0.f); }
                *(float2*)&C[(long long)r1 * ldc + col] = make_float2(v0, v1);
            }
        }
    }
}

// ---------------- elementwise / reduction kernels ----------------

__global__ void add_pe_k(float* __restrict__ h, const float* __restrict__ temb)
{
    long long idx = (long long)blockIdx.x * 256 + threadIdx.x;
    if (idx >= (long long)NTOK * CD) return;
    int d = (int)(idx & (CD-1));
    long long bs = idx >> 9;
    int s  = (int)(bs & (CS-1));
    int bb = (int)(bs >> 10);
    int i2 = d & ~1;
    float dv  = expf((float)i2 * (-9.210340371976184f / (float)CD));
    float ang = (float)s * dv;
    float pe  = (d & 1) ? cosf(ang) : sinf(ang);
    h[idx] += pe + temb[(long long)bb*CD + d];
}

__global__ __launch_bounds__(256)
void softmax1024_k(float* __restrict__ X)
{
    long long row = blockIdx.x;
    float4* x = (float4*)(X + row * 1024);
    int tid = threadIdx.x;
    float4 v = x[tid];
    __shared__ float red[8];

    float m = fmaxf(fmaxf(v.x, v.y), fmaxf(v.z, v.w));
    #pragma unroll
    for (int off = 16; off > 0; off >>= 1)
        m = fmaxf(m, __shfl_xor_sync(0xffffffffu, m, off));
    if ((tid & 31) == 0) red[tid >> 5] = m;
    __syncthreads();
    m = red[0];
    #pragma unroll
    for (int w = 1; w < 8; w++) m = fmaxf(m, red[w]);

    v.x = __expf(v.x - m); v.y = __expf(v.y - m);
    v.z = __expf(v.z - m); v.w = __expf(v.w - m);
    float s = v.x + v.y + v.z + v.w;
    #pragma unroll
    for (int off = 16; off > 0; off >>= 1)
        s += __shfl_xor_sync(0xffffffffu, s, off);
    __syncthreads();
    if ((tid & 31) == 0) red[tid >> 5] = s;
    __syncthreads();
    s = red[0];
    #pragma unroll
    for (int w = 1; w < 8; w++) s += red[w];

    float inv = 1.f / s;
    v.x *= inv; v.y *= inv; v.z *= inv; v.w *= inv;
    x[tid] = v;
}

__global__ void softmax_rows_k(float* __restrict__ X, int ncols)
{
    long long row = blockIdx.x;
    float* x = X + row * (long long)ncols;
    __shared__ float red[256];
    int tid = threadIdx.x;
    float m = -3.0e38f;
    for (int c = tid; c < ncols; c += 256) m = fmaxf(m, x[c]);
    red[tid] = m; __syncthreads();
    for (int off = 128; off > 0; off >>= 1) {
        if (tid < off) red[tid] = fmaxf(red[tid], red[tid+off]);
        __syncthreads();
    }
    float mx = red[0];
    __syncthreads();
    float s = 0.f;
    for (int c = tid; c < ncols; c += 256) { float e = __expf(x[c]-mx); x[c] = e; s += e; }
    red[tid] = s; __syncthreads();
    for (int off = 128; off > 0; off >>= 1) {
        if (tid < off) red[tid] += red[tid+off];
        __syncthreads();
    }
    float inv = 1.f / red[0];
    for (int c = tid; c < ncols; c += 256) x[c] *= inv;
}

__global__ void layernorm512_k(float* __restrict__ X, const float* __restrict__ g,
                               const float* __restrict__ b)
{
    long long row = blockIdx.x;
    float* x = X + row * (long long)CD;
    __shared__ float red[256];
    int tid = threadIdx.x;
    float v0 = x[tid], v1 = x[tid+256];
    red[tid] = v0 + v1; __syncthreads();
    for (int off = 128; off > 0; off >>= 1) {
        if (tid < off) red[tid] += red[tid+off];
        __syncthreads();
    }
    float mu = red[0] * (1.f/512.f);
    __syncthreads();
    float d0 = v0 - mu, d1 = v1 - mu;
    red[tid] = d0*d0 + d1*d1; __syncthreads();
    for (int off = 128; off > 0; off >>= 1) {
        if (tid < off) red[tid] += red[tid+off];
        __syncthreads();
    }
    float var = red[0] * (1.f/512.f);
    float rs = 1.f / sqrtf(var + 1e-5f);
    x[tid]     = d0*rs*g[tid]     + b[tid];
    x[tid+256] = d1*rs*g[tid+256] + b[tid+256];
}

__global__ void bank_prep_k(const float* __restrict__ Phi, const float* __restrict__ Sig,
                            const float* __restrict__ Size,
                            float* __restrict__ p2, float* __restrict__ kb)
{
    int i = blockIdx.x * 256 + threadIdx.x;
    if (i >= CB*CM) return;
    const float* ph = Phi + (long long)i*CD;
    const float* sg = Sig + (long long)i*CD;
    float s = 0.f, s2 = 0.f;
    for (int d = 0; d < CD; d++) { s += ph[d]*ph[d]; s2 += sg[d]*sg[d]; }
    p2[i] = s;
    kb[i] = 0.3f * logf(Size[i] + 1e-6f) - 0.5f * (s2 * (1.f/(float)CD));
}

__global__ void bank_scores_k(float* __restrict__ Sdot, const float* __restrict__ phidot,
                              const float* __restrict__ p2, const float* __restrict__ kb)
{
    long long idx = (long long)blockIdx.x * 256 + threadIdx.x;
    if (idx >= (long long)CB*CH*CM*CM) return;
    int n = (int)(idx & (CM-1));
    long long t = idx >> 8;
    int m = (int)(t & (CM-1));
    long long t2 = t >> 8;
    int bb = (int)(t2 >> 3);
    float d2 = p2[bb*CM + m] + p2[bb*CM + n]
             - 2.f * phidot[((long long)bb*CM + m)*CM + n];
    Sdot[idx] = Sdot[idx] - d2 * (1.f/(float)CD) + kb[bb*CM + n];
}

__global__ void router_k(const float* __restrict__ logits, const float* __restrict__ h,
                         const float* __restrict__ Z, float* __restrict__ out)
{
    int row = blockIdx.x;
    int bb  = row >> 10;
    const float* lg = logits + (long long)row * CM;
    __shared__ float sv[256];
    __shared__ float rv[256];
    __shared__ int   ri[256];
    __shared__ float topv[4];
    __shared__ int   topi[4];
    __shared__ float w[4];
    int tid = threadIdx.x;
    sv[tid] = lg[tid];
    __syncthreads();
    for (int kk = 0; kk < 4; kk++) {
        rv[tid] = sv[tid]; ri[tid] = tid;
        __syncthreads();
        for (int off = 128; off > 0; off >>= 1) {
            if (tid < off) {
                float v2 = rv[tid+off]; int i2 = ri[tid+off];
                if (v2 > rv[tid] || (v2 == rv[tid] && i2 < ri[tid])) { rv[tid] = v2; ri[tid] = i2; }
            }
            __syncthreads();
        }
        if (tid == 0) {
            topv[kk] = rv[0]; topi[kk] = ri[0];
            sv[ri[0]] = -3.0e38f;
        }
        __syncthreads();
    }
    if (tid == 0) {
        float mx = topv[0];
        float e0 = __expf(topv[0]-mx), e1 = __expf(topv[1]-mx),
              e2 = __expf(topv[2]-mx), e3 = __expf(topv[3]-mx);
        float inv = 1.f / (e0+e1+e2+e3);
        w[0]=e0*inv; w[1]=e1*inv; w[2]=e2*inv; w[3]=e3*inv;
    }
    __syncthreads();
    const float* hr = h + (long long)row*CD;
    float w0=w[0], w1=w[1], w2=w[2], w3=w[3];
    const float* z0 = Z + ((long long)bb*CM + topi[0])*CD;
    const float* z1 = Z + ((long long)bb*CM + topi[1])*CD;
    const float* z2 = Z + ((long long)bb*CM + topi[2])*CD;
    const float* z3 = Z + ((long long)bb*CM + topi[3])*CD;
    for (int d = tid; d < CD; d += 256)
        out[(long long)row*CD + d] = hr[d] + w0*z0[d] + w1*z1[d] + w2*z2[d] + w3*z3[d];
}

// ---------------- host side ----------------

enum GMode { G_PLAIN, G_BIAS, G_BIAS_RES, G_BIAS_RELU, G_TRANS };

constexpr int SA_F   = 128 * 20;                 // floats per A stage
constexpr int SHM_TR   = 3 * (SA_F + 128 * 20) * 4;   // 61440 B (BN128 TRB)
constexpr int SHM_128  = 3 * (SA_F + 16 * 136) * 4;   // 56832 B (BN128)
constexpr int SHM_64   = 3 * (SA_F + 16 * 72) * 4;    // 44544 B (BN64)

static inline void gemm(GMode mode, int bn, const float* A, const float* Bm, float* C,
                        const float* bias, const float* Res,
                        int Mr, int Nc, int Kd, int lda, int ldb, int ldc,
                        int batches, int Hb,
                        long long sAb, long long sAh,
                        long long sBb, long long sBh,
                        long long sCb, long long sCh, float alpha)
{
    dim3 grid(Nc / bn, Mr / 128, batches);
    if (bn == 64) {
        cudaFuncSetAttribute(gemm_ca<64,false,false,false,false>,
                             cudaFuncAttributeMaxDynamicSharedMemorySize, SHM_64);
        gemm_ca<64,false,false,false,false><<<grid,256,SHM_64>>>(
            A,Bm,C,bias,Res,Kd,lda,ldb,ldc,Hb,sAb,sAh,sBb,sBh,sCb,sCh,alpha);
        return;
    }
    switch (mode) {
    case G_PLAIN:
        cudaFuncSetAttribute(gemm_ca<128,false,false,false,false>,
                             cudaFuncAttributeMaxDynamicSharedMemorySize, SHM_128);
        gemm_ca<128,false,false,false,false><<<grid,256,SHM_128>>>(
            A,Bm,C,bias,Res,Kd,lda,ldb,ldc,Hb,sAb,sAh,sBb,sBh,sCb,sCh,alpha); break;
    case G_BIAS:
        cudaFuncSetAttribute(gemm_ca<128,false,true,false,false>,
                             cudaFuncAttributeMaxDynamicSharedMemorySize, SHM_128);
        gemm_ca<128,false,true,false,false><<<grid,256,SHM_128>>>(
            A,Bm,C,bias,Res,Kd,lda,ldb,ldc,Hb,sAb,sAh,sBb,sBh,sCb,sCh,alpha); break;
    case G_BIAS_RES:
        cudaFuncSetAttribute(gemm_ca<128,false,true,false,true>,
                             cudaFuncAttributeMaxDynamicSharedMemorySize, SHM_128);
        gemm_ca<128,false,true,false,true><<<grid,256,SHM_128>>>(
            A,Bm,C,bias,Res,Kd,lda,ldb,ldc,Hb,sAb,sAh,sBb,sBh,sCb,sCh,alpha); break;
    case G_BIAS_RELU:
        cudaFuncSetAttribute(gemm_ca<128,false,true,true,false>,
                             cudaFuncAttributeMaxDynamicSharedMemorySize, SHM_128);
        gemm_ca<128,false,true,true,false><<<grid,256,SHM_128>>>(
            A,Bm,C,bias,Res,Kd,lda,ldb,ldc,Hb,sAb,sAh,sBb,sBh,sCb,sCh,alpha); break;
    case G_TRANS:
        cudaFuncSetAttribute(gemm_ca<128,true,false,false,false>,
                             cudaFuncAttributeMaxDynamicSharedMemorySize, SHM_TR);
        gemm_ca<128,true,false,false,false><<<grid,256,SHM_TR>>>(
            A,Bm,C,bias,Res,Kd,lda,ldb,ldc,Hb,sAb,sAh,sBb,sBh,sCb,sCh,alpha); break;
    }
}

extern "C" void kernel_launch(void* const* d_in, const int* in_sizes, int n_in,
                              void* d_out, int out_size)
{
    const float* x_t      = (const float*)d_in[0];
    const float* t_embed  = (const float*)d_in[1];
    const float* Phi      = (const float*)d_in[2];
    const float* Sig      = (const float*)d_in[3];
    const float* Size     = (const float*)d_in[4];
    /* d_in[5] = mask: all-True, ignored */
    const float* Win      = (const float*)d_in[6];
    const float* b_in     = (const float*)d_in[7];
    const float* Wout     = (const float*)d_in[8];
    const float* b_out    = (const float*)d_in[9];
    const float* enc_Wqkv = (const float*)d_in[10];
    const float* enc_bqkv = (const float*)d_in[11];
    const float* enc_Wo   = (const float*)d_in[12];
    const float* enc_bo   = (const float*)d_in[13];
    const float* ln1_g    = (const float*)d_in[14];
    const float* ln1_b    = (const float*)d_in[15];
    const float* ln2_g    = (const float*)d_in[16];
    const float* ln2_b    = (const float*)d_in[17];
    const float* ff_W1    = (const float*)d_in[18];
    const float* ff_b1    = (const float*)d_in[19];
    const float* ff_W2    = (const float*)d_in[20];
    const float* ff_b2    = (const float*)d_in[21];
    const float* sa_Wq    = (const float*)d_in[22];
    const float* sa_Wk    = (const float*)d_in[23];
    const float* sa_Wv    = (const float*)d_in[24];
    const float* sa_Wo    = (const float*)d_in[25];
    const float* rt_Wq    = (const float*)d_in[26];

    float* sc = nullptr;
    cudaGetSymbolAddress((void**)&sc, g_scratch);
    float* h      = sc + O_H;
    float* qkv    = sc + O_QKV;
    float* scores = sc + O_SC;
    float* attno  = sc + O_AO;
    float* ff     = sc + O_FF;
    float* bq     = sc + O_BQ;
    float* bk     = sc + O_BK;
    float* bv     = sc + O_BV;
    float* zc     = sc + O_ZC;
    float* Zb     = sc + O_Z;
    float* phidot = sc + O_PD;
    float* p2     = sc + O_P2;
    float* kb     = sc + O_KB;
    float* hq     = sc + O_HQ;
    float* lgts   = sc + O_LG;
    float* routed = sc + O_RT;

    const float scaleDH = 0.125f;
    const float scaleD  = 0.04419417382415922f;

    // ---- input proj + PE + t_embed ----
    gemm(G_BIAS, 128, x_t, Win, h, b_in, nullptr,
         NTOK, CD, CIN, CIN, CD, CD, 1, 1, 0,0,0,0,0,0, 1.f);
    add_pe_k<<<(NTOK*(long long)CD + 255)/256, 256>>>(h, t_embed);

    // ---- encoder layers ----
    for (int l = 0; l < CL; l++) {
        const float* Wqkv = enc_Wqkv + (long long)l*CD*3*CD;
        const float* bqkv = enc_bqkv + (long long)l*3*CD;
        const float* Wo   = enc_Wo   + (long long)l*CD*CD;
        const float* bo   = enc_bo   + (long long)l*CD;

        gemm(G_BIAS, 128, h, Wqkv, qkv, bqkv, nullptr,
             NTOK, 3*CD, CD, CD, 3*CD, 3*CD, 1, 1, 0,0,0,0,0,0, 1.f);

        gemm(G_TRANS, 128, qkv, qkv + CD, scores, nullptr, nullptr,
             CS, CS, CDH, 3*CD, 3*CD, CS,
             CB*CH, CH,
             (long long)CS*3*CD, CDH,
             (long long)CS*3*CD, CDH,
             (long long)CH*CS*CS, (long long)CS*CS, scaleDH);

        softmax1024_k<<<CB*CH*CS, 256>>>(scores);

        gemm(G_PLAIN, 64, scores, qkv + 2*CD, attno, nullptr, nullptr,
             CS, CDH, CS, CS, 3*CD, CD,
             CB*CH, CH,
             (long long)CH*CS*CS, (long long)CS*CS,
             (long long)CS*3*CD, CDH,
             (long long)CS*CD, CDH, 1.f);

        gemm(G_BIAS_RES, 128, attno, Wo, h, bo, h,
             NTOK, CD, CD, CD, CD, CD, 1, 1, 0,0,0,0,0,0, 1.f);
        layernorm512_k<<<NTOK, 256>>>(h, ln1_g + (long long)l*CD, ln1_b + (long long)l*CD);

        gemm(G_BIAS_RELU, 128, h, ff_W1 + (long long)l*CD*CDFF, ff,
             ff_b1 + (long long)l*CDFF, nullptr,
             NTOK, CDFF, CD, CD, CDFF, CDFF, 1, 1, 0,0,0,0,0,0, 1.f);
        gemm(G_BIAS_RES, 128, ff, ff_W2 + (long long)l*CDFF*CD, h,
             ff_b2 + (long long)l*CD, h,
             NTOK, CD, CDFF, CDFF, CD, CD, 1, 1, 0,0,0,0,0,0, 1.f);
        layernorm512_k<<<NTOK, 256>>>(h, ln2_g + (long long)l*CD, ln2_b + (long long)l*CD);
    }

    // ---- SetBankAttention ----
    gemm(G_PLAIN, 128, Phi, sa_Wq, bq, nullptr, nullptr, CB*CM, CD, CD, CD, CD, CD, 1,1,0,0,0,0,0,0, 1.f);
    gemm(G_PLAIN, 128, Phi, sa_Wk, bk, nullptr, nullptr, CB*CM, CD, CD, CD, CD, CD, 1,1,0,0,0,0,0,0, 1.f);
    gemm(G_PLAIN, 128, Phi, sa_Wv, bv, nullptr, nullptr, CB*CM, CD, CD, CD, CD, CD, 1,1,0,0,0,0,0,0, 1.f);

    gemm(G_TRANS, 128, Phi, Phi, phidot, nullptr, nullptr,
         CM, CM, CD, CD, CD, CM,
         CB, 1,
         (long long)CM*CD, 0, (long long)CM*CD, 0,
         (long long)CM*CM, 0, 1.f);

    gemm(G_TRANS, 128, bq, bk, scores, nullptr, nullptr,
         CM, CM, CDH, CD, CD, CM,
         CB*CH, CH,
         (long long)CM*CD, CDH,
         (long long)CM*CD, CDH,
         (long long)CH*CM*CM, (long long)CM*CM, scaleDH);

    bank_prep_k<<<(CB*CM + 255)/256, 256>>>(Phi, Sig, Size, p2, kb);
    bank_scores_k<<<((long long)CB*CH*CM*CM + 255)/256, 256>>>(scores, phidot, p2, kb);
    softmax_rows_k<<<CB*CH*CM, 256>>>(scores, CM);

    gemm(G_PLAIN, 64, scores, bv, zc, nullptr, nullptr,
         CM, CDH, CM, CM, CD, CD,
         CB*CH, CH,
         (long long)CH*CM*CM, (long long)CM*CM,
         (long long)CM*CD, CDH,
         (long long)CM*CD, CDH, 1.f);

    gemm(G_PLAIN, 128, zc, sa_Wo, Zb, nullptr, nullptr, CB*CM, CD, CD, CD, CD, CD, 1,1,0,0,0,0,0,0, 1.f);

    // ---- router ----
    gemm(G_PLAIN, 128, h, rt_Wq, hq, nullptr, nullptr, NTOK, CD, CD, CD, CD, CD, 1,1,0,0,0,0,0,0, 1.f);
    gemm(G_TRANS, 128, hq, Phi, lgts, nullptr, nullptr,
         CS, CM, CD, CD, CD, CM,
         CB, 1,
         (long long)CS*CD, 0, (long long)CM*CD, 0,
         (long long)CS*CM, 0, scaleD);

    router_k<<<NTOK, 256>>>(lgts, h, Zb, routed);

    // ---- output proj ----
    gemm(G_BIAS, 128, routed, Wout, (float*)d_out, b_out, nullptr,
         NTOK, CIN, CD, CD, CIN, CIN, 1, 1, 0,0,0,0,0,0, 1.f);
}